// round 1
// baseline (speedup 1.0000x reference)
#include <cuda_runtime.h>
#include <cuda_bf16.h>
#include <math.h>

#define BB   128
#define TT   256
#define SS   64
#define DIN  3
#define HH   512
#define KK   10
#define CSLN 60
#define DOUT 121
#define G4H  2048
#define XD   575   // DIN + CSLN + HH
#define XD1  63    // DIN + CSLN

#define NB 128
#define NT 256

// ---------------- device scratch (static, no allocation) ----------------
__device__ float g_h1[BB * HH];          // row layout [b][h] (attention reads rows)
__device__ float g_h1T[2][HH * BB];      // double-buffered transposed h1
__device__ float g_c1T[HH * BB];
__device__ float g_h2T[2][HH * BB];
__device__ float g_c2T[HH * BB];
__device__ float g_p[BB * 3 * KK];
__device__ float g_xT[TT * DIN * BB];
__device__ float g_winT[TT * CSLN * BB];
__device__ float g_h1seqT[TT * HH * BB];     // 64 MB
__device__ float g_gates2[TT * G4H * BB];    // 256 MB (precomputed input gates, layer 2)
__device__ float g_yT[TT * HH * BB];         // 64 MB
__device__ unsigned g_cnt = 0;
__device__ volatile unsigned g_gen = 0;

__device__ __forceinline__ float sigf(float x) { return 1.0f / (1.0f + expf(-x)); }

// grid-wide barrier: all NB blocks are resident (NB=128 <= 148 SMs, 1 block/SM)
__device__ __forceinline__ void gbar() {
    __syncthreads();
    if (threadIdx.x == 0) {
        unsigned gen = g_gen;
        __threadfence();
        if (atomicAdd(&g_cnt, 1) == gridDim.x - 1) {
            g_cnt = 0;
            __threadfence();
            g_gen = gen + 1;
        } else {
            while (g_gen == gen) { __nanosleep(32); }
        }
    }
    __syncthreads();
}

// ---------------- init: state copies, p=0, x transpose ----------------
__global__ void init_kernel(const float* __restrict__ x,
                            const float* __restrict__ h1h, const float* __restrict__ h1c,
                            const float* __restrict__ h2h, const float* __restrict__ h2c) {
    int idx = blockIdx.x * blockDim.x + threadIdx.x;
    if (idx < BB * HH) {
        int b = idx / HH, h = idx % HH;
        float v = h1h[idx];
        g_h1[idx] = v;
        g_h1T[0][h * BB + b] = v;
        g_c1T[h * BB + b] = h1c[idx];
        g_h2T[0][h * BB + b] = h2h[idx];
        g_c2T[h * BB + b] = h2c[idx];
    }
    int i2 = idx - BB * HH;
    if (i2 >= 0 && i2 < BB * 3 * KK) g_p[i2] = 0.0f;
    int i3 = idx - BB * HH - BB * 3 * KK;
    if (i3 >= 0 && i3 < TT * DIN * BB) {
        int b = i3 % BB;
        int r = i3 / BB;
        int t = r / DIN, i = r % DIN;
        g_xT[i3] = x[(b * TT + t) * DIN + i];
    }
}

// ---------------- scan 1: attention + LSTMCell, persistent ----------------
// block b: attention for batch b; gates for hidden units [4b, 4b+4), all batches
__global__ void scan1_kernel(const float* __restrict__ sent,
                             const float* __restrict__ W_ih, const float* __restrict__ W_hh,
                             const float* __restrict__ b_cell,
                             const float* __restrict__ W1, const float* __restrict__ b1) {
    extern __shared__ float sm[];
    float* wS   = sm;                 // 16 * 575
    float* xS   = wS + 16 * XD;       // 64 * 128
    float* hb   = xS + 64 * BB;       // 512
    float* gS   = hb + HH;            // 16 * 128
    float* ipS  = gS + 16 * BB;       // 32
    float* pS   = ipS + 32;           // 32
    float* phiS = pS + 32;            // 64

    int tid = threadIdx.x;
    int blk = blockIdx.x;
    int b   = blk;
    int hu0 = blk * 4;

    // persistent weight tile: local row r -> (g4 = r&3, hl = r>>2), gate row g4*512 + hu0 + hl
    for (int i = tid; i < 16 * XD; i += NT) {
        int rr = i / XD, k = i % XD;
        int g4 = rr & 3, hl = rr >> 2;
        int grow = g4 * HH + hu0 + hl;
        wS[i] = (k < XD1) ? W_ih[grow * XD1 + k] : W_hh[grow * HH + (k - XD1)];
    }
    __syncthreads();

    int r = tid >> 4;        // 0..15 local gate row
    int bg = tid & 15;       // batch group of 8
    int lane = tid & 31, wid = tid >> 5;
    int lb = tid & 127, lq = tid >> 7;

    for (int t = 0; t < TT; t++) {
        // ---- phase A: attention window for batch b ----
        for (int i = tid; i < HH; i += NT) hb[i] = g_h1[b * HH + i];
        __syncthreads();
        for (int j = wid; j < 3 * KK; j += 8) {
            float s = 0.0f;
            const float* w1r = W1 + j * HH;
            #pragma unroll
            for (int m = 0; m < 16; m++) {
                int id = lane + 32 * m;
                s += hb[id] * w1r[id];
            }
            for (int o = 16; o > 0; o >>= 1) s += __shfl_down_sync(0xffffffffu, s, o);
            if (lane == 0) ipS[j] = expf(s + b1[j]);
        }
        __syncthreads();
        if (tid < 3 * KK) {
            float pn = ipS[tid];
            if (tid >= 2 * KK) pn -= g_p[b * 3 * KK + tid];
            g_p[b * 3 * KK + tid] = pn;
            pS[tid] = pn;
        }
        __syncthreads();
        if (tid < SS) {
            float u = (float)(tid + 1);
            float s = 0.0f;
            #pragma unroll
            for (int k = 0; k < KK; k++) {
                float d = pS[2 * KK + k] - u;
                s += pS[k] * expf(-pS[KK + k] * d * d);
            }
            phiS[tid] = s;
        }
        __syncthreads();
        if (tid < CSLN) {
            float s = 0.0f;
            const float* sb = sent + b * SS * CSLN + tid;
            #pragma unroll 8
            for (int ss = 0; ss < SS; ss++) s += phiS[ss] * sb[ss * CSLN];
            g_winT[(t * CSLN + tid) * BB + b] = s;
        }
        gbar();

        // ---- phase B: gates [16 rows x 128 batches], K = 575 ----
        float acc[8];
        #pragma unroll
        for (int j = 0; j < 8; j++) acc[j] = 0.0f;
        const float* h1rd = g_h1T[t & 1];

        for (int k0 = 0; k0 < XD; k0 += 64) {
            int cnt = min(64, XD - k0);
            for (int kk = lq; kk < cnt; kk += 2) {
                int k = k0 + kk;
                float v;
                if (k < DIN)       v = g_xT[(t * DIN + k) * BB + lb];
                else if (k < XD1)  v = g_winT[(t * CSLN + (k - DIN)) * BB + lb];
                else               v = h1rd[(k - XD1) * BB + lb];
                xS[kk * BB + lb] = v;
            }
            __syncthreads();
            const float* wr = wS + r * XD + k0;
            const float4* x4 = (const float4*)xS;
            for (int kk = 0; kk < cnt; kk++) {
                float w = wr[kk];
                float4 a0 = x4[kk * 32 + bg * 2];
                float4 a1 = x4[kk * 32 + bg * 2 + 1];
                acc[0] += w * a0.x; acc[1] += w * a0.y; acc[2] += w * a0.z; acc[3] += w * a0.w;
                acc[4] += w * a1.x; acc[5] += w * a1.y; acc[6] += w * a1.z; acc[7] += w * a1.w;
            }
            __syncthreads();
        }
        {
            int g4 = r & 3, hl = r >> 2;
            float bias = b_cell[g4 * HH + hu0 + hl];
            #pragma unroll
            for (int j = 0; j < 8; j++) gS[r * BB + bg * 8 + j] = acc[j] + bias;
        }
        __syncthreads();

        // ---- state update for 4 hidden units x 128 batches ----
        float* h1wr = g_h1T[(t + 1) & 1];
        for (int idx = tid; idx < 4 * BB; idx += NT) {
            int hl = idx >> 7, bb2 = idx & 127;
            int hu = hu0 + hl;
            float gi = sigf(gS[(hl * 4 + 0) * BB + bb2]);
            float gf = sigf(gS[(hl * 4 + 1) * BB + bb2]);
            float gg = tanhf(gS[(hl * 4 + 2) * BB + bb2]);
            float go = sigf(gS[(hl * 4 + 3) * BB + bb2]);
            float c = gf * g_c1T[hu * BB + bb2] + gi * gg;
            float h = go * tanhf(c);
            g_c1T[hu * BB + bb2] = c;
            h1wr[hu * BB + bb2] = h;
            g_h1[bb2 * HH + hu] = h;
            g_h1seqT[(t * HH + hu) * BB + bb2] = h;
        }
        gbar();
    }
}

// ---------------- layer-2 input gates precompute (parallel GEMM) ----------------
// C[t][row][b] = W_ih_l[row,:] . X[t][:,b] + b_l[row], X = [x; win; h1]
__global__ void gemm_pre_kernel(const float* __restrict__ W, const float* __restrict__ bias) {
    __shared__ float a_s[128 * 33];   // [r][33] padded
    __shared__ float x_s[32 * 128];   // [k][b]
    int t  = blockIdx.x >> 4;
    int rt = blockIdx.x & 15;
    int tid = threadIdx.x;
    int tx = tid & 15, ty = tid >> 4;
    int lk = tid & 31, lr0 = tid >> 5;
    int lb = tid & 127, lq = tid >> 7;

    float acc[8][8];
    #pragma unroll
    for (int i = 0; i < 8; i++)
        #pragma unroll
        for (int j = 0; j < 8; j++) acc[i][j] = 0.0f;

    for (int k0 = 0; k0 < XD; k0 += 32) {
        for (int rr = lr0; rr < 128; rr += 8) {
            int row = rt * 128 + rr;
            int k = k0 + lk;
            a_s[rr * 33 + lk] = (k < XD) ? W[row * XD + k] : 0.0f;
        }
        for (int kk = lq; kk < 32; kk += 2) {
            int k = k0 + kk;
            float v = 0.0f;
            if (k < XD) {
                if (k < DIN)      v = g_xT[(t * DIN + k) * BB + lb];
                else if (k < XD1) v = g_winT[(t * CSLN + (k - DIN)) * BB + lb];
                else              v = g_h1seqT[(t * HH + (k - XD1)) * BB + lb];
            }
            x_s[kk * BB + lb] = v;
        }
        __syncthreads();
        for (int kk = 0; kk < 32; kk++) {
            float wf[8];
            #pragma unroll
            for (int i = 0; i < 8; i++) wf[i] = a_s[(ty * 8 + i) * 33 + kk];
            float4 xa = ((const float4*)x_s)[kk * 32 + tx * 2];
            float4 xb = ((const float4*)x_s)[kk * 32 + tx * 2 + 1];
            float xf[8] = {xa.x, xa.y, xa.z, xa.w, xb.x, xb.y, xb.z, xb.w};
            #pragma unroll
            for (int i = 0; i < 8; i++)
                #pragma unroll
                for (int j = 0; j < 8; j++) acc[i][j] += wf[i] * xf[j];
        }
        __syncthreads();
    }
    #pragma unroll
    for (int i = 0; i < 8; i++) {
        int row = rt * 128 + ty * 8 + i;
        float bi = bias[row];
        #pragma unroll
        for (int j = 0; j < 8; j++)
            g_gates2[(t * G4H + row) * BB + tx * 8 + j] = acc[i][j] + bi;
    }
}

// ---------------- scan 2: second LSTM, persistent ----------------
__global__ void scan2_kernel(const float* __restrict__ W_hh_l) {
    extern __shared__ float sm[];
    float* wS = sm;              // 16 * 512
    float* xS = wS + 16 * HH;    // 64 * 128
    float* gS = xS + 64 * BB;    // 16 * 128

    int tid = threadIdx.x, blk = blockIdx.x;
    int hu0 = blk * 4;
    for (int i = tid; i < 16 * HH; i += NT) {
        int rr = i / HH, k = i % HH;
        int g4 = rr & 3, hl = rr >> 2;
        wS[i] = W_hh_l[(g4 * HH + hu0 + hl) * HH + k];
    }
    __syncthreads();

    int r = tid >> 4, bg = tid & 15;
    int lb = tid & 127, lq = tid >> 7;

    for (int t = 0; t < TT; t++) {
        float acc[8];
        #pragma unroll
        for (int j = 0; j < 8; j++) acc[j] = 0.0f;
        const float* hrd = g_h2T[t & 1];

        for (int k0 = 0; k0 < HH; k0 += 64) {
            for (int kk = lq; kk < 64; kk += 2)
                xS[kk * BB + lb] = hrd[(k0 + kk) * BB + lb];
            __syncthreads();
            const float* wr = wS + r * HH + k0;
            const float4* x4 = (const float4*)xS;
            for (int kk = 0; kk < 64; kk++) {
                float w = wr[kk];
                float4 a0 = x4[kk * 32 + bg * 2];
                float4 a1 = x4[kk * 32 + bg * 2 + 1];
                acc[0] += w * a0.x; acc[1] += w * a0.y; acc[2] += w * a0.z; acc[3] += w * a0.w;
                acc[4] += w * a1.x; acc[5] += w * a1.y; acc[6] += w * a1.z; acc[7] += w * a1.w;
            }
            __syncthreads();
        }
        {
            int g4 = r & 3, hl = r >> 2;
            int grow = g4 * HH + hu0 + hl;
            const float* pre = g_gates2 + (t * G4H + grow) * BB + bg * 8;
            #pragma unroll
            for (int j = 0; j < 8; j++) gS[r * BB + bg * 8 + j] = acc[j] + pre[j];
        }
        __syncthreads();

        float* hwr = g_h2T[(t + 1) & 1];
        for (int idx = tid; idx < 4 * BB; idx += NT) {
            int hl = idx >> 7, bb2 = idx & 127;
            int hu = hu0 + hl;
            float gi = sigf(gS[(hl * 4 + 0) * BB + bb2]);
            float gf = sigf(gS[(hl * 4 + 1) * BB + bb2]);
            float gg = tanhf(gS[(hl * 4 + 2) * BB + bb2]);
            float go = sigf(gS[(hl * 4 + 3) * BB + bb2]);
            float c = gf * g_c2T[hu * BB + bb2] + gi * gg;
            float h = go * tanhf(c);
            g_c2T[hu * BB + bb2] = c;
            hwr[hu * BB + bb2] = h;
            g_yT[(t * HH + hu) * BB + bb2] = h;
        }
        gbar();
    }
}

// ---------------- final projection: out[b*T+t][o] = y . W2^T + b2 ----------------
__global__ void final_kernel(const float* __restrict__ W2, const float* __restrict__ b2,
                             float* __restrict__ out) {
    __shared__ float w_s[128 * 33];
    __shared__ float y_s[32 * 128];
    int t = blockIdx.x;
    int tid = threadIdx.x, tx = tid & 15, ty = tid >> 4;
    int lk = tid & 31, lo0 = tid >> 5;
    int lb = tid & 127, lq = tid >> 7;

    float acc[8][8];
    #pragma unroll
    for (int i = 0; i < 8; i++)
        #pragma unroll
        for (int j = 0; j < 8; j++) acc[i][j] = 0.0f;

    for (int k0 = 0; k0 < HH; k0 += 32) {
        for (int oo = lo0; oo < 128; oo += 8)
            w_s[oo * 33 + lk] = (oo < DOUT) ? W2[oo * HH + k0 + lk] : 0.0f;
        for (int kk = lq; kk < 32; kk += 2)
            y_s[kk * BB + lb] = g_yT[(t * HH + k0 + kk) * BB + lb];
        __syncthreads();
        for (int kk = 0; kk < 32; kk++) {
            float wf[8];
            #pragma unroll
            for (int i = 0; i < 8; i++) wf[i] = w_s[(ty * 8 + i) * 33 + kk];
            float4 xa = ((const float4*)y_s)[kk * 32 + tx * 2];
            float4 xb = ((const float4*)y_s)[kk * 32 + tx * 2 + 1];
            float xf[8] = {xa.x, xa.y, xa.z, xa.w, xb.x, xb.y, xb.z, xb.w};
            #pragma unroll
            for (int i = 0; i < 8; i++)
                #pragma unroll
                for (int j = 0; j < 8; j++) acc[i][j] += wf[i] * xf[j];
        }
        __syncthreads();
    }
    #pragma unroll
    for (int i = 0; i < 8; i++) {
        int o = ty * 8 + i;
        if (o < DOUT) {
            float bi = b2[o];
            #pragma unroll
            for (int j = 0; j < 8; j++) {
                int bb2 = tx * 8 + j;
                out[(size_t)(bb2 * TT + t) * DOUT + o] = acc[i][j] + bi;
            }
        }
    }
}

// ---------------- epilogue: final states ----------------
__global__ void epi_kernel(float* __restrict__ out) {
    int idx = blockIdx.x * blockDim.x + threadIdx.x;
    if (idx >= BB * HH) return;
    int b = idx / HH, h = idx % HH;
    size_t base = (size_t)BB * TT * DOUT;
    out[base + idx]               = g_h1[idx];
    out[base + BB * HH + idx]     = g_c1T[h * BB + b];
    out[base + 2 * BB * HH + idx] = g_h2T[0][h * BB + b];   // t=255 wrote buffer 0
    out[base + 3 * BB * HH + idx] = g_c2T[h * BB + b];
}

extern "C" void kernel_launch(void* const* d_in, const int* in_sizes, int n_in,
                              void* d_out, int out_size) {
    const float* x      = (const float*)d_in[0];
    const float* sent   = (const float*)d_in[1];
    const float* h1h    = (const float*)d_in[2];
    const float* h1c    = (const float*)d_in[3];
    const float* h2h    = (const float*)d_in[4];
    const float* h2c    = (const float*)d_in[5];
    const float* Wihc   = (const float*)d_in[6];
    const float* Whhc   = (const float*)d_in[7];
    const float* bcell  = (const float*)d_in[8];
    const float* Wihl   = (const float*)d_in[9];
    const float* Whhl   = (const float*)d_in[10];
    const float* bl     = (const float*)d_in[11];
    const float* W1     = (const float*)d_in[12];
    const float* b1     = (const float*)d_in[13];
    const float* W2     = (const float*)d_in[14];
    const float* b2     = (const float*)d_in[15];
    float* out = (float*)d_out;

    size_t sm1 = (size_t)(16 * XD + 64 * BB + HH + 16 * BB + 32 + 32 + 64) * sizeof(float);
    size_t sm2 = (size_t)(16 * HH + 64 * BB + 16 * BB) * sizeof(float);
    cudaFuncSetAttribute(scan1_kernel, cudaFuncAttributeMaxDynamicSharedMemorySize, (int)sm1);
    cudaFuncSetAttribute(scan2_kernel, cudaFuncAttributeMaxDynamicSharedMemorySize, (int)sm2);

    int init_n = BB * HH + BB * 3 * KK + TT * DIN * BB;
    init_kernel<<<(init_n + NT - 1) / NT, NT>>>(x, h1h, h1c, h2h, h2c);
    scan1_kernel<<<NB, NT, sm1>>>(sent, Wihc, Whhc, bcell, W1, b1);
    gemm_pre_kernel<<<TT * 16, 256>>>(Wihl, bl);
    scan2_kernel<<<NB, NT, sm2>>>(Whhl);
    final_kernel<<<TT, 256>>>(W2, b2, out);
    epi_kernel<<<(BB * HH + NT - 1) / NT, NT>>>(out);
}

// round 2
// speedup vs baseline: 1.7898x; 1.7898x over previous
#include <cuda_runtime.h>
#include <cuda_bf16.h>
#include <math.h>

#define BB   128
#define TT   256
#define SS   64
#define DIN  3
#define HH   512
#define KK   10
#define CSLN 60
#define DOUT 121
#define G4H  2048
#define XD   575   // DIN + CSLN + HH
#define XD1  63    // DIN + CSLN

#define NB  128
#define NTS 512    // scan kernel threads

typedef unsigned long long ull;

__device__ __forceinline__ ull pk2(float lo, float hi) {
    ull r; asm("mov.b64 %0,{%1,%2};" : "=l"(r) : "f"(lo), "f"(hi)); return r;
}
__device__ __forceinline__ void upk2(float& lo, float& hi, ull v) {
    asm("mov.b64 {%0,%1},%2;" : "=f"(lo), "=f"(hi) : "l"(v));
}
__device__ __forceinline__ ull fma2(ull a, ull b, ull c) {
    ull d; asm("fma.rn.f32x2 %0,%1,%2,%3;" : "=l"(d) : "l"(a), "l"(b), "l"(c)); return d;
}
__device__ __forceinline__ ull add2(ull a, ull b) {
    ull d; asm("add.rn.f32x2 %0,%1,%2;" : "=l"(d) : "l"(a), "l"(b)); return d;
}

// ---------------- device scratch ----------------
__device__ float g_h1[BB * HH];
__device__ float g_h1T[2][HH * BB];
__device__ float g_c1T[HH * BB];
__device__ float g_h2T[2][HH * BB];
__device__ float g_c2T[HH * BB];
__device__ float g_p[BB * 3 * KK];
__device__ float g_xT[TT * DIN * BB];
__device__ float g_winT[TT * CSLN * BB];
__device__ float g_h1seqT[TT * HH * BB];
__device__ float g_gates2[TT * G4H * BB];
__device__ float g_yT[TT * HH * BB];
__device__ unsigned g_cnt = 0;
__device__ volatile unsigned g_gen = 0;

__device__ __forceinline__ float sigf(float x) { return 1.0f / (1.0f + expf(-x)); }

__device__ __forceinline__ void gbar() {
    __syncthreads();
    if (threadIdx.x == 0) {
        unsigned gen = g_gen;
        __threadfence();
        if (atomicAdd(&g_cnt, 1) == gridDim.x - 1) {
            g_cnt = 0;
            __threadfence();
            g_gen = gen + 1;
        } else {
            while (g_gen == gen) { __nanosleep(32); }
        }
    }
    __syncthreads();
}

// ---------------- init ----------------
__global__ void init_kernel(const float* __restrict__ x,
                            const float* __restrict__ h1h, const float* __restrict__ h1c,
                            const float* __restrict__ h2h, const float* __restrict__ h2c) {
    int idx = blockIdx.x * blockDim.x + threadIdx.x;
    if (idx < BB * HH) {
        int b = idx / HH, h = idx % HH;
        float v = h1h[idx];
        g_h1[idx] = v;
        g_h1T[0][h * BB + b] = v;
        g_c1T[h * BB + b] = h1c[idx];
        g_h2T[0][h * BB + b] = h2h[idx];
        g_c2T[h * BB + b] = h2c[idx];
    }
    int i2 = idx - BB * HH;
    if (i2 >= 0 && i2 < BB * 3 * KK) g_p[i2] = 0.0f;
    int i3 = idx - BB * HH - BB * 3 * KK;
    if (i3 >= 0 && i3 < TT * DIN * BB) {
        int b = i3 % BB;
        int r = i3 / BB;
        int t = r / DIN, i = r % DIN;
        g_xT[i3] = x[(b * TT + t) * DIN + i];
    }
}

// feature fetch for scan1: kg in [0,XD)
__device__ __forceinline__ float fetch1(int t, int kg, int bb, const float* h1rd) {
    if (kg < DIN)      return g_xT[(t * DIN + kg) * BB + bb];
    else if (kg < XD1) return g_winT[(t * CSLN + (kg - DIN)) * BB + bb];
    else               return h1rd[(kg - XD1) * BB + bb];
}

// ---------------- scan 1: attention + LSTMCell ----------------
// block b: attention batch b; gates for hidden units [4b,4b+4), all batches.
// 512 threads: bg=tid&7 (16 batches), rg=(tid>>3)&7 (2 rows), kc=tid>>6 (k-split 8)
__global__ __launch_bounds__(NTS, 1)
void scan1_kernel(const float* __restrict__ sent,
                  const float* __restrict__ W_ih, const float* __restrict__ W_hh,
                  const float* __restrict__ b_cell,
                  const float* __restrict__ W1, const float* __restrict__ b1) {
    extern __shared__ __align__(16) char smraw[];
    ull*   wS2  = (ull*)smraw;                    // [XD][16] pairs {w,w}
    float* w1S  = (float*)(wS2 + 16 * XD);        // [30][512]
    float* xS   = w1S + 30 * HH;                  // [128][128]  (also partial buf)
    float* gS   = xS + 128 * 128;                 // [16][128]
    float* hb   = gS + 16 * BB;                   // 512
    float* ipS  = hb + HH;                        // 32
    float* pS   = ipS + 32;                       // 32
    float* phiS = pS + 32;                        // 64

    int tid = threadIdx.x;
    int b   = blockIdx.x;
    int hu0 = b * 4;
    int bg = tid & 7, rg = (tid >> 3) & 7, kc = tid >> 6;
    int lane = tid & 31, wid = tid >> 5;

    // persistent duplicated weight pairs: wS2[k*16 + r] = {w,w}
    for (int i = tid; i < 16 * XD; i += NTS) {
        int k = i >> 4, r = i & 15;
        int g4 = r & 3, hl = r >> 2;
        int grow = g4 * HH + hu0 + hl;
        float w = (k < XD1) ? W_ih[grow * XD1 + k] : W_hh[grow * HH + (k - XD1)];
        wS2[i] = pk2(w, w);
    }
    for (int i = tid; i < 30 * HH; i += NTS) w1S[i] = W1[i];

    // reduction constants: pair p=tid -> row prow0, p+512 -> prow1; col pair bp
    int prow0 = tid >> 6, prow1 = prow0 + 8;
    int bp = tid & 63;
    float bias0 = b_cell[(prow0 & 3) * HH + hu0 + (prow0 >> 2)];
    float bias1 = b_cell[(prow1 & 3) * HH + hu0 + (prow1 >> 2)];
    ull bpr0 = pk2(bias0, bias0), bpr1 = pk2(bias1, bias1);
    __syncthreads();

    for (int t = 0; t < TT; t++) {
        // ---- phase A: attention window for batch b ----
        if (tid < HH) hb[tid] = g_h1[b * HH + tid];
        __syncthreads();
        for (int j = wid; j < 3 * KK; j += 16) {
            float s = 0.0f;
            const float* w1r = w1S + j * HH;
            #pragma unroll
            for (int m = 0; m < 16; m++) {
                int id = lane + 32 * m;
                s += hb[id] * w1r[id];
            }
            for (int o = 16; o > 0; o >>= 1) s += __shfl_down_sync(0xffffffffu, s, o);
            if (lane == 0) ipS[j] = expf(s + b1[j]);
        }
        __syncthreads();
        if (tid < 3 * KK) {
            float pn = ipS[tid];
            if (tid >= 2 * KK) pn -= g_p[b * 3 * KK + tid];
            g_p[b * 3 * KK + tid] = pn;
            pS[tid] = pn;
        }
        __syncthreads();
        if (tid < SS) {
            float u = (float)(tid + 1);
            float s = 0.0f;
            #pragma unroll
            for (int k = 0; k < KK; k++) {
                float d = pS[2 * KK + k] - u;
                s += pS[k] * expf(-pS[KK + k] * d * d);
            }
            phiS[tid] = s;
        }
        __syncthreads();
        if (tid < CSLN) {
            float s = 0.0f;
            const float* sb = sent + b * SS * CSLN + tid;
            #pragma unroll 8
            for (int ss = 0; ss < SS; ss++) s += phiS[ss] * sb[ss * CSLN];
            g_winT[(t * CSLN + tid) * BB + b] = s;
        }
        gbar();

        // ---- phase B: gates [16 x 128], K=575, prefetched 128-k tiles ----
        const float* h1rd = g_h1T[t & 1];
        ull acc[2][8];
        #pragma unroll
        for (int r = 0; r < 2; r++)
            #pragma unroll
            for (int j = 0; j < 8; j++) acc[r][j] = 0ull;

        float pf[32];
        #pragma unroll
        for (int j = 0; j < 32; j++) {
            int e = tid + j * NTS;
            pf[j] = fetch1(t, e >> 7, e & 127, h1rd);
        }
        for (int tile = 0; tile < 5; tile++) {
            int kbase = tile * 128;
            int ks = (tile == 4) ? (XD - 512) : 128;   // 63 on last tile
            __syncthreads();
            #pragma unroll
            for (int j = 0; j < 32; j++) {
                int e = tid + j * NTS;
                if (e < ks * 128) xS[e] = pf[j];
            }
            __syncthreads();
            if (tile < 4) {
                int kb2 = kbase + 128;
                int ks2 = (tile == 3) ? (XD - 512) : 128;
                #pragma unroll
                for (int j = 0; j < 32; j++) {
                    int e = tid + j * NTS;
                    if (e < ks2 * 128) pf[j] = fetch1(t, kb2 + (e >> 7), e & 127, h1rd);
                }
            }
            int k0 = kc * 16;
            int k1 = min(ks, k0 + 16);
            for (int kk = k0; kk < k1; kk++) {
                ulonglong2 wv = *(const ulonglong2*)&wS2[(kbase + kk) * 16 + rg * 2];
                const ulonglong2* xp = (const ulonglong2*)&xS[kk * 128 + bg * 16];
                ulonglong2 xa = xp[0], xb = xp[1], xc = xp[2], xd = xp[3];
                acc[0][0] = fma2(wv.x, xa.x, acc[0][0]);
                acc[0][1] = fma2(wv.x, xa.y, acc[0][1]);
                acc[0][2] = fma2(wv.x, xb.x, acc[0][2]);
                acc[0][3] = fma2(wv.x, xb.y, acc[0][3]);
                acc[0][4] = fma2(wv.x, xc.x, acc[0][4]);
                acc[0][5] = fma2(wv.x, xc.y, acc[0][5]);
                acc[0][6] = fma2(wv.x, xd.x, acc[0][6]);
                acc[0][7] = fma2(wv.x, xd.y, acc[0][7]);
                acc[1][0] = fma2(wv.y, xa.x, acc[1][0]);
                acc[1][1] = fma2(wv.y, xa.y, acc[1][1]);
                acc[1][2] = fma2(wv.y, xb.x, acc[1][2]);
                acc[1][3] = fma2(wv.y, xb.y, acc[1][3]);
                acc[1][4] = fma2(wv.y, xc.x, acc[1][4]);
                acc[1][5] = fma2(wv.y, xc.y, acc[1][5]);
                acc[1][6] = fma2(wv.y, xd.x, acc[1][6]);
                acc[1][7] = fma2(wv.y, xd.y, acc[1][7]);
            }
        }
        // ---- reduce 8 k-partials ----
        __syncthreads();
        ull* part = (ull*)xS;   // [kc][16][64]
        #pragma unroll
        for (int r = 0; r < 2; r++)
            #pragma unroll
            for (int j = 0; j < 8; j++)
                part[(kc * 16 + rg * 2 + r) * 64 + bg * 8 + j] = acc[r][j];
        __syncthreads();
        {
            ull s0 = bpr0, s1 = bpr1;
            #pragma unroll
            for (int q = 0; q < 8; q++) {
                s0 = add2(s0, part[(q * 16 + prow0) * 64 + bp]);
                s1 = add2(s1, part[(q * 16 + prow1) * 64 + bp]);
            }
            ((ull*)gS)[prow0 * 64 + bp] = s0;
            ((ull*)gS)[prow1 * 64 + bp] = s1;
        }
        __syncthreads();

        // ---- state update: exactly 512 = 4 units x 128 batches ----
        {
            float* h1wr = g_h1T[(t + 1) & 1];
            int hl = tid >> 7, bb2 = tid & 127;
            int hu = hu0 + hl;
            float gi = sigf(gS[(hl * 4 + 0) * BB + bb2]);
            float gf = sigf(gS[(hl * 4 + 1) * BB + bb2]);
            float gg = tanhf(gS[(hl * 4 + 2) * BB + bb2]);
            float go = sigf(gS[(hl * 4 + 3) * BB + bb2]);
            float c = gf * g_c1T[hu * BB + bb2] + gi * gg;
            float h = go * tanhf(c);
            g_c1T[hu * BB + bb2] = c;
            h1wr[hu * BB + bb2] = h;
            g_h1[bb2 * HH + hu] = h;
            g_h1seqT[(t * HH + hu) * BB + bb2] = h;
        }
        gbar();
    }
}

// ---------------- layer-2 input gates (parallel GEMM, f32x2) ----------------
__global__ __launch_bounds__(256)
void gemm_pre_kernel(const float* __restrict__ W, const float* __restrict__ bias) {
    extern __shared__ __align__(16) char smraw[];
    ull*   a_s = (ull*)smraw;            // [128][33] pairs {w,w}
    float* x_s = (float*)(a_s + 128 * 33);  // [32][128]
    int t  = blockIdx.x >> 4;
    int rt = blockIdx.x & 15;
    int tid = threadIdx.x;
    int tx = tid & 15, ty = tid >> 4;

    ull acc[8][4];
    #pragma unroll
    for (int i = 0; i < 8; i++)
        #pragma unroll
        for (int j = 0; j < 4; j++) acc[i][j] = 0ull;

    for (int k0 = 0; k0 < XD; k0 += 32) {
        for (int i = tid; i < 128 * 32; i += 256) {
            int row = i >> 5, kk = i & 31;
            int k = k0 + kk;
            float w = (k < XD) ? W[(rt * 128 + row) * XD + k] : 0.0f;
            a_s[row * 33 + kk] = pk2(w, w);
        }
        for (int i = tid; i < 32 * 128; i += 256) {
            int kk = i >> 7, bb = i & 127;
            int k = k0 + kk;
            float v = 0.0f;
            if (k < XD) {
                if (k < DIN)      v = g_xT[(t * DIN + k) * BB + bb];
                else if (k < XD1) v = g_winT[(t * CSLN + (k - DIN)) * BB + bb];
                else              v = g_h1seqT[(t * HH + (k - XD1)) * BB + bb];
            }
            x_s[i] = v;
        }
        __syncthreads();
        #pragma unroll 4
        for (int kk = 0; kk < 32; kk++) {
            const ulonglong2* xp = (const ulonglong2*)&x_s[kk * 128 + tx * 8];
            ulonglong2 xa = xp[0], xb = xp[1];
            #pragma unroll
            for (int i = 0; i < 8; i++) {
                ull w2 = a_s[(ty * 8 + i) * 33 + kk];
                acc[i][0] = fma2(w2, xa.x, acc[i][0]);
                acc[i][1] = fma2(w2, xa.y, acc[i][1]);
                acc[i][2] = fma2(w2, xb.x, acc[i][2]);
                acc[i][3] = fma2(w2, xb.y, acc[i][3]);
            }
        }
        __syncthreads();
    }
    #pragma unroll
    for (int i = 0; i < 8; i++) {
        int row = rt * 128 + ty * 8 + i;
        float bi = bias[row];
        ull bpr = pk2(bi, bi);
        ull* op = (ull*)&g_gates2[(size_t)(t * G4H + row) * BB + tx * 8];
        #pragma unroll
        for (int j = 0; j < 4; j++) op[j] = add2(acc[i][j], bpr);
    }
}

// ---------------- scan 2: second LSTM ----------------
__global__ __launch_bounds__(NTS, 1)
void scan2_kernel(const float* __restrict__ W_hh_l) {
    extern __shared__ __align__(16) char smraw[];
    ull*   wS2 = (ull*)smraw;              // [512][16] pairs
    float* xS  = (float*)(wS2 + 16 * HH);  // [128][128]
    float* gS  = xS + 128 * 128;           // [16][128]

    int tid = threadIdx.x;
    int hu0 = blockIdx.x * 4;
    int bg = tid & 7, rg = (tid >> 3) & 7, kc = tid >> 6;

    for (int i = tid; i < 16 * HH; i += NTS) {
        int k = i >> 4, r = i & 15;
        int g4 = r & 3, hl = r >> 2;
        float w = W_hh_l[(g4 * HH + hu0 + hl) * HH + k];
        wS2[i] = pk2(w, w);
    }
    int prow0 = tid >> 6, prow1 = prow0 + 8;
    int bp = tid & 63;
    int grow0 = (prow0 & 3) * HH + hu0 + (prow0 >> 2);
    int grow1 = (prow1 & 3) * HH + hu0 + (prow1 >> 2);
    __syncthreads();

    for (int t = 0; t < TT; t++) {
        const float* hrd = g_h2T[t & 1];
        ull acc[2][8];
        #pragma unroll
        for (int r = 0; r < 2; r++)
            #pragma unroll
            for (int j = 0; j < 8; j++) acc[r][j] = 0ull;

        float pf[32];
        #pragma unroll
        for (int j = 0; j < 32; j++) pf[j] = hrd[tid + j * NTS];
        for (int tile = 0; tile < 4; tile++) {
            __syncthreads();
            #pragma unroll
            for (int j = 0; j < 32; j++) xS[tid + j * NTS] = pf[j];
            __syncthreads();
            if (tile < 3) {
                const float* src = hrd + (tile + 1) * 128 * 128;
                #pragma unroll
                for (int j = 0; j < 32; j++) pf[j] = src[tid + j * NTS];
            }
            int kbase = tile * 128;
            int k0 = kc * 16;
            #pragma unroll 2
            for (int kk = k0; kk < k0 + 16; kk++) {
                ulonglong2 wv = *(const ulonglong2*)&wS2[(kbase + kk) * 16 + rg * 2];
                const ulonglong2* xp = (const ulonglong2*)&xS[kk * 128 + bg * 16];
                ulonglong2 xa = xp[0], xb = xp[1], xc = xp[2], xd = xp[3];
                acc[0][0] = fma2(wv.x, xa.x, acc[0][0]);
                acc[0][1] = fma2(wv.x, xa.y, acc[0][1]);
                acc[0][2] = fma2(wv.x, xb.x, acc[0][2]);
                acc[0][3] = fma2(wv.x, xb.y, acc[0][3]);
                acc[0][4] = fma2(wv.x, xc.x, acc[0][4]);
                acc[0][5] = fma2(wv.x, xc.y, acc[0][5]);
                acc[0][6] = fma2(wv.x, xd.x, acc[0][6]);
                acc[0][7] = fma2(wv.x, xd.y, acc[0][7]);
                acc[1][0] = fma2(wv.y, xa.x, acc[1][0]);
                acc[1][1] = fma2(wv.y, xa.y, acc[1][1]);
                acc[1][2] = fma2(wv.y, xb.x, acc[1][2]);
                acc[1][3] = fma2(wv.y, xb.y, acc[1][3]);
                acc[1][4] = fma2(wv.y, xc.x, acc[1][4]);
                acc[1][5] = fma2(wv.y, xc.y, acc[1][5]);
                acc[1][6] = fma2(wv.y, xd.x, acc[1][6]);
                acc[1][7] = fma2(wv.y, xd.y, acc[1][7]);
            }
        }
        __syncthreads();
        ull* part = (ull*)xS;
        #pragma unroll
        for (int r = 0; r < 2; r++)
            #pragma unroll
            for (int j = 0; j < 8; j++)
                part[(kc * 16 + rg * 2 + r) * 64 + bg * 8 + j] = acc[r][j];
        __syncthreads();
        {
            const ull* pre0 = (const ull*)&g_gates2[(size_t)(t * G4H + grow0) * BB];
            const ull* pre1 = (const ull*)&g_gates2[(size_t)(t * G4H + grow1) * BB];
            ull s0 = pre0[bp], s1 = pre1[bp];
            #pragma unroll
            for (int q = 0; q < 8; q++) {
                s0 = add2(s0, part[(q * 16 + prow0) * 64 + bp]);
                s1 = add2(s1, part[(q * 16 + prow1) * 64 + bp]);
            }
            ((ull*)gS)[prow0 * 64 + bp] = s0;
            ((ull*)gS)[prow1 * 64 + bp] = s1;
        }
        __syncthreads();
        {
            float* hwr = g_h2T[(t + 1) & 1];
            int hl = tid >> 7, bb2 = tid & 127;
            int hu = hu0 + hl;
            float gi = sigf(gS[(hl * 4 + 0) * BB + bb2]);
            float gf = sigf(gS[(hl * 4 + 1) * BB + bb2]);
            float gg = tanhf(gS[(hl * 4 + 2) * BB + bb2]);
            float go = sigf(gS[(hl * 4 + 3) * BB + bb2]);
            float c = gf * g_c2T[hu * BB + bb2] + gi * gg;
            float h = go * tanhf(c);
            g_c2T[hu * BB + bb2] = c;
            hwr[hu * BB + bb2] = h;
            g_yT[(t * HH + hu) * BB + bb2] = h;
        }
        gbar();
    }
}

// ---------------- final projection ----------------
__global__ void final_kernel(const float* __restrict__ W2, const float* __restrict__ b2,
                             float* __restrict__ out) {
    __shared__ float w_s[128 * 33];
    __shared__ float y_s[32 * 128];
    int t = blockIdx.x;
    int tid = threadIdx.x, tx = tid & 15, ty = tid >> 4;
    int lk = tid & 31, lo0 = tid >> 5;
    int lb = tid & 127, lq = tid >> 7;

    float acc[8][8];
    #pragma unroll
    for (int i = 0; i < 8; i++)
        #pragma unroll
        for (int j = 0; j < 8; j++) acc[i][j] = 0.0f;

    for (int k0 = 0; k0 < HH; k0 += 32) {
        for (int oo = lo0; oo < 128; oo += 8)
            w_s[oo * 33 + lk] = (oo < DOUT) ? W2[oo * HH + k0 + lk] : 0.0f;
        for (int kk = lq; kk < 32; kk += 2)
            y_s[kk * BB + lb] = g_yT[(t * HH + k0 + kk) * BB + lb];
        __syncthreads();
        for (int kk = 0; kk < 32; kk++) {
            float wf[8];
            #pragma unroll
            for (int i = 0; i < 8; i++) wf[i] = w_s[(ty * 8 + i) * 33 + kk];
            float4 xa = ((const float4*)y_s)[kk * 32 + tx * 2];
            float4 xb = ((const float4*)y_s)[kk * 32 + tx * 2 + 1];
            float xf[8] = {xa.x, xa.y, xa.z, xa.w, xb.x, xb.y, xb.z, xb.w};
            #pragma unroll
            for (int i = 0; i < 8; i++)
                #pragma unroll
                for (int j = 0; j < 8; j++) acc[i][j] += wf[i] * xf[j];
        }
        __syncthreads();
    }
    #pragma unroll
    for (int i = 0; i < 8; i++) {
        int o = ty * 8 + i;
        if (o < DOUT) {
            float bi = b2[o];
            #pragma unroll
            for (int j = 0; j < 8; j++) {
                int bb2 = tx * 8 + j;
                out[(size_t)(bb2 * TT + t) * DOUT + o] = acc[i][j] + bi;
            }
        }
    }
}

// ---------------- epilogue ----------------
__global__ void epi_kernel(float* __restrict__ out) {
    int idx = blockIdx.x * blockDim.x + threadIdx.x;
    if (idx >= BB * HH) return;
    int b = idx / HH, h = idx % HH;
    size_t base = (size_t)BB * TT * DOUT;
    out[base + idx]               = g_h1[idx];
    out[base + BB * HH + idx]     = g_c1T[h * BB + b];
    out[base + 2 * BB * HH + idx] = g_h2T[0][h * BB + b];
    out[base + 3 * BB * HH + idx] = g_c2T[h * BB + b];
}

extern "C" void kernel_launch(void* const* d_in, const int* in_sizes, int n_in,
                              void* d_out, int out_size) {
    const float* x      = (const float*)d_in[0];
    const float* sent   = (const float*)d_in[1];
    const float* h1h    = (const float*)d_in[2];
    const float* h1c    = (const float*)d_in[3];
    const float* h2h    = (const float*)d_in[4];
    const float* h2c    = (const float*)d_in[5];
    const float* Wihc   = (const float*)d_in[6];
    const float* Whhc   = (const float*)d_in[7];
    const float* bcell  = (const float*)d_in[8];
    const float* Wihl   = (const float*)d_in[9];
    const float* Whhl   = (const float*)d_in[10];
    const float* bl     = (const float*)d_in[11];
    const float* W1     = (const float*)d_in[12];
    const float* b1     = (const float*)d_in[13];
    const float* W2     = (const float*)d_in[14];
    const float* b2     = (const float*)d_in[15];
    float* out = (float*)d_out;

    size_t sm1 = (size_t)16 * XD * 8 + (size_t)30 * HH * 4 + 128 * 128 * 4
               + 16 * BB * 4 + HH * 4 + (32 + 32 + 64) * 4;           // ~211 KB
    size_t sm2 = (size_t)16 * HH * 8 + 128 * 128 * 4 + 16 * BB * 4;   // ~139 KB
    size_t smG = (size_t)128 * 33 * 8 + 32 * 128 * 4;                 // ~50 KB
    cudaFuncSetAttribute(scan1_kernel, cudaFuncAttributeMaxDynamicSharedMemorySize, (int)sm1);
    cudaFuncSetAttribute(scan2_kernel, cudaFuncAttributeMaxDynamicSharedMemorySize, (int)sm2);
    cudaFuncSetAttribute(gemm_pre_kernel, cudaFuncAttributeMaxDynamicSharedMemorySize, (int)smG);

    int init_n = BB * HH + BB * 3 * KK + TT * DIN * BB;
    init_kernel<<<(init_n + 255) / 256, 256>>>(x, h1h, h1c, h2h, h2c);
    scan1_kernel<<<NB, NTS, sm1>>>(sent, Wihc, Whhc, bcell, W1, b1);
    gemm_pre_kernel<<<TT * 16, 256, smG>>>(Wihl, bl);
    scan2_kernel<<<NB, NTS, sm2>>>(Whhl);
    final_kernel<<<TT, 256>>>(W2, b2, out);
    epi_kernel<<<(BB * HH + 255) / 256, 256>>>(out);
}

// round 3
// speedup vs baseline: 3.4104x; 1.9055x over previous
#include <cuda_runtime.h>
#include <cuda_bf16.h>
#include <math.h>

#define BB   128
#define TT   256
#define SS   64
#define DIN  3
#define HH   512
#define KK   10
#define CSLN 60
#define DOUT 121
#define G4H  2048
#define XD   575   // DIN + CSLN + HH
#define XD1  63    // DIN + CSLN

#define NB  128
#define NTS 512    // scan kernel threads

typedef unsigned long long ull;

__device__ __forceinline__ ull pk2(float lo, float hi) {
    ull r; asm("mov.b64 %0,{%1,%2};" : "=l"(r) : "f"(lo), "f"(hi)); return r;
}
__device__ __forceinline__ ull fma2(ull a, ull b, ull c) {
    ull d; asm("fma.rn.f32x2 %0,%1,%2,%3;" : "=l"(d) : "l"(a), "l"(b), "l"(c)); return d;
}
__device__ __forceinline__ ull add2(ull a, ull b) {
    ull d; asm("add.rn.f32x2 %0,%1,%2;" : "=l"(d) : "l"(a), "l"(b)); return d;
}

// ---------------- device scratch ----------------
__device__ float g_h1[BB * HH];
__device__ float g_h1T[2][HH * BB];
__device__ float g_c1T[HH * BB];
__device__ float g_h2T[2][HH * BB];
__device__ float g_c2T[HH * BB];
__device__ float g_p[BB * 3 * KK];
__device__ float g_xT[TT * DIN * BB];
__device__ float g_winT[TT * CSLN * BB];
__device__ float g_h1seqT[TT * HH * BB];
__device__ float g_gates2[TT * G4H * BB];
__device__ float g_yT[TT * HH * BB];
__device__ unsigned g_cnt = 0;
__device__ volatile unsigned g_gen = 0;

__device__ __forceinline__ float sigf(float x) { return 1.0f / (1.0f + expf(-x)); }

__device__ __forceinline__ void gbar() {
    __syncthreads();
    if (threadIdx.x == 0) {
        unsigned gen = g_gen;
        __threadfence();
        if (atomicAdd(&g_cnt, 1) == gridDim.x - 1) {
            g_cnt = 0;
            __threadfence();
            g_gen = gen + 1;
        } else {
            while (g_gen == gen) { }
        }
    }
    __syncthreads();
}

// ---------------- init ----------------
__global__ void init_kernel(const float* __restrict__ x,
                            const float* __restrict__ h1h, const float* __restrict__ h1c,
                            const float* __restrict__ h2h, const float* __restrict__ h2c) {
    int idx = blockIdx.x * blockDim.x + threadIdx.x;
    if (idx < BB * HH) {
        int b = idx / HH, h = idx % HH;
        float v = h1h[idx];
        g_h1[idx] = v;
        g_h1T[0][h * BB + b] = v;
        g_c1T[h * BB + b] = h1c[idx];
        g_h2T[0][h * BB + b] = h2h[idx];
        g_c2T[h * BB + b] = h2c[idx];
    }
    int i2 = idx - BB * HH;
    if (i2 >= 0 && i2 < BB * 3 * KK) g_p[i2] = 0.0f;
    int i3 = idx - BB * HH - BB * 3 * KK;
    if (i3 >= 0 && i3 < TT * DIN * BB) {
        int b = i3 % BB;
        int r = i3 / BB;
        int t = r / DIN, i = r % DIN;
        g_xT[i3] = x[(b * TT + t) * DIN + i];
    }
}

// feature fetch for scan1: kg in [0,XD)
__device__ __forceinline__ float fetch1(int t, int kg, int bb, const float* h1rd) {
    if (kg < DIN)      return g_xT[(t * DIN + kg) * BB + bb];
    else if (kg < XD1) return g_winT[(t * CSLN + (kg - DIN)) * BB + bb];
    else               return h1rd[(kg - XD1) * BB + bb];
}

// ---------------- scan 1: attention + LSTMCell ----------------
__global__ __launch_bounds__(NTS, 1)
void scan1_kernel(const float* __restrict__ sent,
                  const float* __restrict__ W_ih, const float* __restrict__ W_hh,
                  const float* __restrict__ b_cell,
                  const float* __restrict__ W1, const float* __restrict__ b1) {
    extern __shared__ __align__(16) char smraw[];
    ull*   wS2  = (ull*)smraw;                    // [XD][16] pairs {w,w}
    float* w1S  = (float*)(wS2 + 16 * XD);        // [30][512]
    float* xS   = w1S + 30 * HH;                  // [128][128]  (also partial buf)
    float* gS   = xS + 128 * 128;                 // [16][128]
    float* hb   = gS + 16 * BB;                   // 512
    float* ipS  = hb + HH;                        // 32
    float* pS   = ipS + 32;                       // 32
    float* phiS = pS + 32;                        // 64

    int tid = threadIdx.x;
    int b   = blockIdx.x;
    int hu0 = b * 4;
    int bg = tid & 7, rg = (tid >> 3) & 7, kc = tid >> 6;
    int lane = tid & 31, wid = tid >> 5;

    for (int i = tid; i < 16 * XD; i += NTS) {
        int k = i >> 4, r = i & 15;
        int g4 = r & 3, hl = r >> 2;
        int grow = g4 * HH + hu0 + hl;
        float w = (k < XD1) ? W_ih[grow * XD1 + k] : W_hh[grow * HH + (k - XD1)];
        wS2[i] = pk2(w, w);
    }
    for (int i = tid; i < 30 * HH; i += NTS) w1S[i] = W1[i];

    int prow0 = tid >> 6, prow1 = prow0 + 8;
    int bp = tid & 63;
    float bias0 = b_cell[(prow0 & 3) * HH + hu0 + (prow0 >> 2)];
    float bias1 = b_cell[(prow1 & 3) * HH + hu0 + (prow1 >> 2)];
    ull bpr0 = pk2(bias0, bias0), bpr1 = pk2(bias1, bias1);
    __syncthreads();

    for (int t = 0; t < TT; t++) {
        // ---- phase A: attention window for batch b ----
        if (tid < HH) hb[tid] = g_h1[b * HH + tid];
        __syncthreads();
        for (int j = wid; j < 3 * KK; j += 16) {
            float s = 0.0f;
            const float* w1r = w1S + j * HH;
            #pragma unroll
            for (int m = 0; m < 16; m++) {
                int id = lane + 32 * m;
                s += hb[id] * w1r[id];
            }
            for (int o = 16; o > 0; o >>= 1) s += __shfl_down_sync(0xffffffffu, s, o);
            if (lane == 0) ipS[j] = expf(s + b1[j]);
        }
        __syncthreads();
        if (tid < 3 * KK) {
            float pn = ipS[tid];
            if (tid >= 2 * KK) pn -= g_p[b * 3 * KK + tid];
            g_p[b * 3 * KK + tid] = pn;
            pS[tid] = pn;
        }
        __syncthreads();
        if (tid < SS) {
            float u = (float)(tid + 1);
            float s = 0.0f;
            #pragma unroll
            for (int k = 0; k < KK; k++) {
                float d = pS[2 * KK + k] - u;
                s += pS[k] * expf(-pS[KK + k] * d * d);
            }
            phiS[tid] = s;
        }
        __syncthreads();
        if (tid < CSLN) {
            float s = 0.0f;
            const float* sb = sent + b * SS * CSLN + tid;
            #pragma unroll 8
            for (int ss = 0; ss < SS; ss++) s += phiS[ss] * sb[ss * CSLN];
            g_winT[(t * CSLN + tid) * BB + b] = s;
        }
        gbar();

        // ---- phase B: gates [16 x 128], K=575 ----
        const float* h1rd = g_h1T[t & 1];
        ull acc[2][8];
        #pragma unroll
        for (int r = 0; r < 2; r++)
            #pragma unroll
            for (int j = 0; j < 8; j++) acc[r][j] = 0ull;

        float pf[32];
        #pragma unroll
        for (int j = 0; j < 32; j++) {
            int e = tid + j * NTS;
            pf[j] = fetch1(t, e >> 7, e & 127, h1rd);
        }
        for (int tile = 0; tile < 5; tile++) {
            int kbase = tile * 128;
            int ks = (tile == 4) ? (XD - 512) : 128;
            __syncthreads();
            #pragma unroll
            for (int j = 0; j < 32; j++) {
                int e = tid + j * NTS;
                if (e < ks * 128) xS[e] = pf[j];
            }
            __syncthreads();
            if (tile < 4) {
                int kb2 = kbase + 128;
                int ks2 = (tile == 3) ? (XD - 512) : 128;
                #pragma unroll
                for (int j = 0; j < 32; j++) {
                    int e = tid + j * NTS;
                    if (e < ks2 * 128) pf[j] = fetch1(t, kb2 + (e >> 7), e & 127, h1rd);
                }
            }
            int k0 = kc * 16;
            int k1 = min(ks, k0 + 16);
            for (int kk = k0; kk < k1; kk++) {
                ulonglong2 wv = *(const ulonglong2*)&wS2[(kbase + kk) * 16 + rg * 2];
                // conflict-free: chunk q at float offset q*32 + bg*4 (16B per lane, 128B/phase)
                ulonglong2 xa = *(const ulonglong2*)&xS[kk * 128 + bg * 4];
                ulonglong2 xb = *(const ulonglong2*)&xS[kk * 128 + 32 + bg * 4];
                ulonglong2 xc = *(const ulonglong2*)&xS[kk * 128 + 64 + bg * 4];
                ulonglong2 xd = *(const ulonglong2*)&xS[kk * 128 + 96 + bg * 4];
                acc[0][0] = fma2(wv.x, xa.x, acc[0][0]);
                acc[0][1] = fma2(wv.x, xa.y, acc[0][1]);
                acc[0][2] = fma2(wv.x, xb.x, acc[0][2]);
                acc[0][3] = fma2(wv.x, xb.y, acc[0][3]);
                acc[0][4] = fma2(wv.x, xc.x, acc[0][4]);
                acc[0][5] = fma2(wv.x, xc.y, acc[0][5]);
                acc[0][6] = fma2(wv.x, xd.x, acc[0][6]);
                acc[0][7] = fma2(wv.x, xd.y, acc[0][7]);
                acc[1][0] = fma2(wv.y, xa.x, acc[1][0]);
                acc[1][1] = fma2(wv.y, xa.y, acc[1][1]);
                acc[1][2] = fma2(wv.y, xb.x, acc[1][2]);
                acc[1][3] = fma2(wv.y, xb.y, acc[1][3]);
                acc[1][4] = fma2(wv.y, xc.x, acc[1][4]);
                acc[1][5] = fma2(wv.y, xc.y, acc[1][5]);
                acc[1][6] = fma2(wv.y, xd.x, acc[1][6]);
                acc[1][7] = fma2(wv.y, xd.y, acc[1][7]);
            }
        }
        // ---- reduce 8 k-partials (pair index = (j>>1)*16 + bg*2 + (j&1) = batch-pair) ----
        __syncthreads();
        ull* part = (ull*)xS;
        #pragma unroll
        for (int r = 0; r < 2; r++)
            #pragma unroll
            for (int j = 0; j < 8; j++)
                part[(kc * 16 + rg * 2 + r) * 64 + (j >> 1) * 16 + bg * 2 + (j & 1)] = acc[r][j];
        __syncthreads();
        {
            ull s0 = bpr0, s1 = bpr1;
            #pragma unroll
            for (int q = 0; q < 8; q++) {
                s0 = add2(s0, part[(q * 16 + prow0) * 64 + bp]);
                s1 = add2(s1, part[(q * 16 + prow1) * 64 + bp]);
            }
            ((ull*)gS)[prow0 * 64 + bp] = s0;
            ((ull*)gS)[prow1 * 64 + bp] = s1;
        }
        __syncthreads();

        // ---- state update ----
        {
            float* h1wr = g_h1T[(t + 1) & 1];
            int hl = tid >> 7, bb2 = tid & 127;
            int hu = hu0 + hl;
            float gi = sigf(gS[(hl * 4 + 0) * BB + bb2]);
            float gf = sigf(gS[(hl * 4 + 1) * BB + bb2]);
            float gg = tanhf(gS[(hl * 4 + 2) * BB + bb2]);
            float go = sigf(gS[(hl * 4 + 3) * BB + bb2]);
            float c = gf * g_c1T[hu * BB + bb2] + gi * gg;
            float h = go * tanhf(c);
            g_c1T[hu * BB + bb2] = c;
            h1wr[hu * BB + bb2] = h;
            g_h1[bb2 * HH + hu] = h;
            g_h1seqT[(t * HH + hu) * BB + bb2] = h;
        }
        gbar();
    }
}

// ---------------- layer-2 input gates (parallel GEMM, f32x2) ----------------
__global__ __launch_bounds__(256)
void gemm_pre_kernel(const float* __restrict__ W, const float* __restrict__ bias) {
    extern __shared__ __align__(16) char smraw[];
    ull*   a_s = (ull*)smraw;               // [128][33] pairs {w,w}
    float* x_s = (float*)(a_s + 128 * 33);  // [32][128]
    int t  = blockIdx.x >> 4;
    int rt = blockIdx.x & 15;
    int tid = threadIdx.x;
    int tx = tid & 15, ty = tid >> 4;

    ull acc[8][4];
    #pragma unroll
    for (int i = 0; i < 8; i++)
        #pragma unroll
        for (int j = 0; j < 4; j++) acc[i][j] = 0ull;

    for (int k0 = 0; k0 < XD; k0 += 32) {
        for (int i = tid; i < 128 * 32; i += 256) {
            int row = i >> 5, kk = i & 31;
            int k = k0 + kk;
            float w = (k < XD) ? W[(rt * 128 + row) * XD + k] : 0.0f;
            a_s[row * 33 + kk] = pk2(w, w);
        }
        for (int i = tid; i < 32 * 128; i += 256) {
            int kk = i >> 7, bb = i & 127;
            int k = k0 + kk;
            float v = 0.0f;
            if (k < XD) {
                if (k < DIN)      v = g_xT[(t * DIN + k) * BB + bb];
                else if (k < XD1) v = g_winT[(t * CSLN + (k - DIN)) * BB + bb];
                else              v = g_h1seqT[(t * HH + (k - XD1)) * BB + bb];
            }
            x_s[i] = v;
        }
        __syncthreads();
        #pragma unroll 4
        for (int kk = 0; kk < 32; kk++) {
            // conflict-free: chunk q at float offset q*64 + tx*4
            ulonglong2 xa = *(const ulonglong2*)&x_s[kk * 128 + tx * 4];
            ulonglong2 xb = *(const ulonglong2*)&x_s[kk * 128 + 64 + tx * 4];
            #pragma unroll
            for (int i = 0; i < 8; i++) {
                ull w2 = a_s[(ty * 8 + i) * 33 + kk];
                acc[i][0] = fma2(w2, xa.x, acc[i][0]);
                acc[i][1] = fma2(w2, xa.y, acc[i][1]);
                acc[i][2] = fma2(w2, xb.x, acc[i][2]);
                acc[i][3] = fma2(w2, xb.y, acc[i][3]);
            }
        }
        __syncthreads();
    }
    #pragma unroll
    for (int i = 0; i < 8; i++) {
        int row = rt * 128 + ty * 8 + i;
        float bi = bias[row];
        ull bpr = pk2(bi, bi);
        ull* gp = (ull*)&g_gates2[(size_t)(t * G4H + row) * BB];
        gp[tx * 2]          = add2(acc[i][0], bpr);
        gp[tx * 2 + 1]      = add2(acc[i][1], bpr);
        gp[32 + tx * 2]     = add2(acc[i][2], bpr);
        gp[32 + tx * 2 + 1] = add2(acc[i][3], bpr);
    }
}

// ---------------- scan 2: second LSTM ----------------
__global__ __launch_bounds__(NTS, 1)
void scan2_kernel(const float* __restrict__ W_hh_l) {
    extern __shared__ __align__(16) char smraw[];
    ull*   wS2 = (ull*)smraw;              // [512][16] pairs
    float* xS  = (float*)(wS2 + 16 * HH);  // [128][128]
    float* gS  = xS + 128 * 128;           // [16][128]

    int tid = threadIdx.x;
    int hu0 = blockIdx.x * 4;
    int bg = tid & 7, rg = (tid >> 3) & 7, kc = tid >> 6;

    for (int i = tid; i < 16 * HH; i += NTS) {
        int k = i >> 4, r = i & 15;
        int g4 = r & 3, hl = r >> 2;
        float w = W_hh_l[(g4 * HH + hu0 + hl) * HH + k];
        wS2[i] = pk2(w, w);
    }
    int prow0 = tid >> 6, prow1 = prow0 + 8;
    int bp = tid & 63;
    int grow0 = (prow0 & 3) * HH + hu0 + (prow0 >> 2);
    int grow1 = (prow1 & 3) * HH + hu0 + (prow1 >> 2);
    __syncthreads();

    for (int t = 0; t < TT; t++) {
        const float* hrd = g_h2T[t & 1];
        ull acc[2][8];
        #pragma unroll
        for (int r = 0; r < 2; r++)
            #pragma unroll
            for (int j = 0; j < 8; j++) acc[r][j] = 0ull;

        float pf[32];
        #pragma unroll
        for (int j = 0; j < 32; j++) pf[j] = hrd[tid + j * NTS];
        for (int tile = 0; tile < 4; tile++) {
            __syncthreads();
            #pragma unroll
            for (int j = 0; j < 32; j++) xS[tid + j * NTS] = pf[j];
            __syncthreads();
            if (tile < 3) {
                const float* src = hrd + (tile + 1) * 128 * 128;
                #pragma unroll
                for (int j = 0; j < 32; j++) pf[j] = src[tid + j * NTS];
            }
            int kbase = tile * 128;
            int k0 = kc * 16;
            #pragma unroll 2
            for (int kk = k0; kk < k0 + 16; kk++) {
                ulonglong2 wv = *(const ulonglong2*)&wS2[(kbase + kk) * 16 + rg * 2];
                ulonglong2 xa = *(const ulonglong2*)&xS[kk * 128 + bg * 4];
                ulonglong2 xb = *(const ulonglong2*)&xS[kk * 128 + 32 + bg * 4];
                ulonglong2 xc = *(const ulonglong2*)&xS[kk * 128 + 64 + bg * 4];
                ulonglong2 xd = *(const ulonglong2*)&xS[kk * 128 + 96 + bg * 4];
                acc[0][0] = fma2(wv.x, xa.x, acc[0][0]);
                acc[0][1] = fma2(wv.x, xa.y, acc[0][1]);
                acc[0][2] = fma2(wv.x, xb.x, acc[0][2]);
                acc[0][3] = fma2(wv.x, xb.y, acc[0][3]);
                acc[0][4] = fma2(wv.x, xc.x, acc[0][4]);
                acc[0][5] = fma2(wv.x, xc.y, acc[0][5]);
                acc[0][6] = fma2(wv.x, xd.x, acc[0][6]);
                acc[0][7] = fma2(wv.x, xd.y, acc[0][7]);
                acc[1][0] = fma2(wv.y, xa.x, acc[1][0]);
                acc[1][1] = fma2(wv.y, xa.y, acc[1][1]);
                acc[1][2] = fma2(wv.y, xb.x, acc[1][2]);
                acc[1][3] = fma2(wv.y, xb.y, acc[1][3]);
                acc[1][4] = fma2(wv.y, xc.x, acc[1][4]);
                acc[1][5] = fma2(wv.y, xc.y, acc[1][5]);
                acc[1][6] = fma2(wv.y, xd.x, acc[1][6]);
                acc[1][7] = fma2(wv.y, xd.y, acc[1][7]);
            }
        }
        __syncthreads();
        ull* part = (ull*)xS;
        #pragma unroll
        for (int r = 0; r < 2; r++)
            #pragma unroll
            for (int j = 0; j < 8; j++)
                part[(kc * 16 + rg * 2 + r) * 64 + (j >> 1) * 16 + bg * 2 + (j & 1)] = acc[r][j];
        __syncthreads();
        {
            const ull* pre0 = (const ull*)&g_gates2[(size_t)(t * G4H + grow0) * BB];
            const ull* pre1 = (const ull*)&g_gates2[(size_t)(t * G4H + grow1) * BB];
            ull s0 = pre0[bp], s1 = pre1[bp];
            #pragma unroll
            for (int q = 0; q < 8; q++) {
                s0 = add2(s0, part[(q * 16 + prow0) * 64 + bp]);
                s1 = add2(s1, part[(q * 16 + prow1) * 64 + bp]);
            }
            ((ull*)gS)[prow0 * 64 + bp] = s0;
            ((ull*)gS)[prow1 * 64 + bp] = s1;
        }
        __syncthreads();
        {
            float* hwr = g_h2T[(t + 1) & 1];
            int hl = tid >> 7, bb2 = tid & 127;
            int hu = hu0 + hl;
            float gi = sigf(gS[(hl * 4 + 0) * BB + bb2]);
            float gf = sigf(gS[(hl * 4 + 1) * BB + bb2]);
            float gg = tanhf(gS[(hl * 4 + 2) * BB + bb2]);
            float go = sigf(gS[(hl * 4 + 3) * BB + bb2]);
            float c = gf * g_c2T[hu * BB + bb2] + gi * gg;
            float h = go * tanhf(c);
            g_c2T[hu * BB + bb2] = c;
            hwr[hu * BB + bb2] = h;
            g_yT[(t * HH + hu) * BB + bb2] = h;
        }
        gbar();
    }
}

// ---------------- final projection ----------------
__global__ void final_kernel(const float* __restrict__ W2, const float* __restrict__ b2,
                             float* __restrict__ out) {
    __shared__ float w_s[128 * 33];
    __shared__ float y_s[32 * 128];
    int t = blockIdx.x;
    int tid = threadIdx.x, tx = tid & 15, ty = tid >> 4;
    int lk = tid & 31, lo0 = tid >> 5;
    int lb = tid & 127, lq = tid >> 7;

    float acc[8][8];
    #pragma unroll
    for (int i = 0; i < 8; i++)
        #pragma unroll
        for (int j = 0; j < 8; j++) acc[i][j] = 0.0f;

    for (int k0 = 0; k0 < HH; k0 += 32) {
        for (int oo = lo0; oo < 128; oo += 8)
            w_s[oo * 33 + lk] = (oo < DOUT) ? W2[oo * HH + k0 + lk] : 0.0f;
        for (int kk = lq; kk < 32; kk += 2)
            y_s[kk * BB + lb] = g_yT[(t * HH + k0 + kk) * BB + lb];
        __syncthreads();
        for (int kk = 0; kk < 32; kk++) {
            float wf[8];
            #pragma unroll
            for (int i = 0; i < 8; i++) wf[i] = w_s[(ty * 8 + i) * 33 + kk];
            // conflict-free: chunk q at float offset q*64 + tx*4
            float4 xa = *(const float4*)&y_s[kk * 128 + tx * 4];
            float4 xb = *(const float4*)&y_s[kk * 128 + 64 + tx * 4];
            float xf[8] = {xa.x, xa.y, xa.z, xa.w, xb.x, xb.y, xb.z, xb.w};
            #pragma unroll
            for (int i = 0; i < 8; i++)
                #pragma unroll
                for (int j = 0; j < 8; j++) acc[i][j] += wf[i] * xf[j];
        }
        __syncthreads();
    }
    #pragma unroll
    for (int i = 0; i < 8; i++) {
        int o = ty * 8 + i;
        if (o < DOUT) {
            float bi = b2[o];
            #pragma unroll
            for (int j = 0; j < 8; j++) {
                int bb2 = (j >> 2) * 64 + tx * 4 + (j & 3);
                out[(size_t)(bb2 * TT + t) * DOUT + o] = acc[i][j] + bi;
            }
        }
    }
}

// ---------------- epilogue ----------------
__global__ void epi_kernel(float* __restrict__ out) {
    int idx = blockIdx.x * blockDim.x + threadIdx.x;
    if (idx >= BB * HH) return;
    int b = idx / HH, h = idx % HH;
    size_t base = (size_t)BB * TT * DOUT;
    out[base + idx]               = g_h1[idx];
    out[base + BB * HH + idx]     = g_c1T[h * BB + b];
    out[base + 2 * BB * HH + idx] = g_h2T[0][h * BB + b];
    out[base + 3 * BB * HH + idx] = g_c2T[h * BB + b];
}

extern "C" void kernel_launch(void* const* d_in, const int* in_sizes, int n_in,
                              void* d_out, int out_size) {
    const float* x      = (const float*)d_in[0];
    const float* sent   = (const float*)d_in[1];
    const float* h1h    = (const float*)d_in[2];
    const float* h1c    = (const float*)d_in[3];
    const float* h2h    = (const float*)d_in[4];
    const float* h2c    = (const float*)d_in[5];
    const float* Wihc   = (const float*)d_in[6];
    const float* Whhc   = (const float*)d_in[7];
    const float* bcell  = (const float*)d_in[8];
    const float* Wihl   = (const float*)d_in[9];
    const float* Whhl   = (const float*)d_in[10];
    const float* bl     = (const float*)d_in[11];
    const float* W1     = (const float*)d_in[12];
    const float* b1     = (const float*)d_in[13];
    const float* W2     = (const float*)d_in[14];
    const float* b2     = (const float*)d_in[15];
    float* out = (float*)d_out;

    size_t sm1 = (size_t)16 * XD * 8 + (size_t)30 * HH * 4 + 128 * 128 * 4
               + 16 * BB * 4 + HH * 4 + (32 + 32 + 64) * 4;
    size_t sm2 = (size_t)16 * HH * 8 + 128 * 128 * 4 + 16 * BB * 4;
    size_t smG = (size_t)128 * 33 * 8 + 32 * 128 * 4;
    cudaFuncSetAttribute(scan1_kernel, cudaFuncAttributeMaxDynamicSharedMemorySize, (int)sm1);
    cudaFuncSetAttribute(scan2_kernel, cudaFuncAttributeMaxDynamicSharedMemorySize, (int)sm2);
    cudaFuncSetAttribute(gemm_pre_kernel, cudaFuncAttributeMaxDynamicSharedMemorySize, (int)smG);

    int init_n = BB * HH + BB * 3 * KK + TT * DIN * BB;
    init_kernel<<<(init_n + 255) / 256, 256>>>(x, h1h, h1c, h2h, h2c);
    scan1_kernel<<<NB, NTS, sm1>>>(sent, Wihc, Whhc, bcell, W1, b1);
    gemm_pre_kernel<<<TT * 16, 256, smG>>>(Wihl, bl);
    scan2_kernel<<<NB, NTS, sm2>>>(Whhl);
    final_kernel<<<TT, 256>>>(W2, b2, out);
    epi_kernel<<<(BB * HH + 255) / 256, 256>>>(out);
}

// round 4
// speedup vs baseline: 3.5926x; 1.0534x over previous
#include <cuda_runtime.h>
#include <cuda_bf16.h>
#include <math.h>

#define BB   128
#define TT   256
#define SS   64
#define DIN  3
#define HH   512
#define KK   10
#define CSLN 60
#define DOUT 121
#define G4H  2048
#define XD   575   // DIN + CSLN + HH
#define XD1  63    // DIN + CSLN

#define NB   128   // scan blocks (barrier count)
#define NBA  148   // total blocks in fused kernel (<= SM count: all resident)
#define NTS  512

typedef unsigned long long ull;

__device__ __forceinline__ ull pk2(float lo, float hi) {
    ull r; asm("mov.b64 %0,{%1,%2};" : "=l"(r) : "f"(lo), "f"(hi)); return r;
}
__device__ __forceinline__ ull fma2(ull a, ull b, ull c) {
    ull d; asm("fma.rn.f32x2 %0,%1,%2,%3;" : "=l"(d) : "l"(a), "l"(b), "l"(c)); return d;
}
__device__ __forceinline__ ull add2(ull a, ull b) {
    ull d; asm("add.rn.f32x2 %0,%1,%2;" : "=l"(d) : "l"(a), "l"(b)); return d;
}

// ---------------- device scratch ----------------
__device__ float g_h1[BB * HH];
__device__ float g_h1T[2][HH * BB];
__device__ float g_c1T[HH * BB];
__device__ float g_h2T[2][HH * BB];
__device__ float g_c2T[HH * BB];
__device__ float g_p[BB * 3 * KK];
__device__ float g_xT[TT * DIN * BB];
__device__ float g_winT[TT * CSLN * BB];
__device__ float g_h1seqT[TT * HH * BB];
__device__ float g_gates2[TT * G4H * BB];
__device__ float g_yT[TT * HH * BB];
__device__ unsigned g_cnt = 0;
__device__ volatile unsigned g_gen = 0;
__device__ unsigned g_ticket = 0;

__device__ __forceinline__ float sigf(float x) { return 1.0f / (1.0f + expf(-x)); }

// barrier across the NB scan blocks only
__device__ __forceinline__ void gbar() {
    __syncthreads();
    if (threadIdx.x == 0) {
        unsigned gen = g_gen;
        __threadfence();
        if (atomicAdd(&g_cnt, 1) == NB - 1) {
            g_cnt = 0;
            __threadfence();
            g_gen = gen + 1;
        } else {
            while (g_gen == gen) { }
        }
    }
    __syncthreads();
}

// ---------------- init ----------------
__global__ void init_kernel(const float* __restrict__ x,
                            const float* __restrict__ h1h, const float* __restrict__ h1c,
                            const float* __restrict__ h2h, const float* __restrict__ h2c) {
    int idx = blockIdx.x * blockDim.x + threadIdx.x;
    if (idx == 0) { g_cnt = 0; g_gen = 0; g_ticket = 0; }
    if (idx < BB * HH) {
        int b = idx / HH, h = idx % HH;
        float v = h1h[idx];
        g_h1[idx] = v;
        g_h1T[0][h * BB + b] = v;
        g_c1T[h * BB + b] = h1c[idx];
        g_h2T[0][h * BB + b] = h2h[idx];
        g_c2T[h * BB + b] = h2c[idx];
    }
    int i2 = idx - BB * HH;
    if (i2 >= 0 && i2 < BB * 3 * KK) g_p[i2] = 0.0f;
    int i3 = idx - BB * HH - BB * 3 * KK;
    if (i3 >= 0 && i3 < TT * DIN * BB) {
        int b = i3 % BB;
        int r = i3 / BB;
        int t = r / DIN, i = r % DIN;
        g_xT[i3] = x[(b * TT + t) * DIN + i];
    }
}

// feature fetch: kg in [0,XD)
__device__ __forceinline__ float fetch1(int t, int kg, int bb, const float* h1rd) {
    if (kg < DIN)      return g_xT[(t * DIN + kg) * BB + bb];
    else if (kg < XD1) return g_winT[(t * CSLN + (kg - DIN)) * BB + bb];
    else               return h1rd[(kg - XD1) * BB + bb];
}
__device__ __forceinline__ float fetch_seq(int t, int kg, int bb) {
    if (kg < DIN)      return g_xT[(t * DIN + kg) * BB + bb];
    else if (kg < XD1) return g_winT[(t * CSLN + (kg - DIN)) * BB + bb];
    else               return g_h1seqT[(t * HH + (kg - XD1)) * BB + bb];
}

// ---------------- gemm work unit: gates2[t] rows [rt*128, rt*128+128) ----------------
// 512 threads: ty=tid>>5 (8 rows each), tx=tid&31 (4 batches = 2 pairs)
__device__ void gemm_unit(int t, int rt, int tid, char* smraw,
                          const float* __restrict__ W, const float* __restrict__ bias) {
    ull*   a_s = (ull*)smraw;               // [128][33] pairs {w,w}
    float* x_s = (float*)(a_s + 128 * 33);  // [32][128]
    int ty = tid >> 5, tx = tid & 31;

    ull acc[8][2];
    #pragma unroll
    for (int i = 0; i < 8; i++) { acc[i][0] = 0ull; acc[i][1] = 0ull; }

    for (int k0 = 0; k0 < XD; k0 += 32) {
        for (int i = tid; i < 128 * 32; i += NTS) {
            int row = i >> 5, kk = i & 31;
            int k = k0 + kk;
            float w = (k < XD) ? W[(rt * 128 + row) * XD + k] : 0.0f;
            a_s[row * 33 + kk] = pk2(w, w);
        }
        for (int i = tid; i < 32 * 128; i += NTS) {
            int kk = i >> 7, bb = i & 127;
            int k = k0 + kk;
            x_s[i] = (k < XD) ? fetch_seq(t, k, bb) : 0.0f;
        }
        __syncthreads();
        #pragma unroll 4
        for (int kk = 0; kk < 32; kk++) {
            ulonglong2 xv = *(const ulonglong2*)&x_s[kk * 128 + tx * 4];
            #pragma unroll
            for (int i = 0; i < 8; i++) {
                ull w2 = a_s[(ty * 8 + i) * 33 + kk];
                acc[i][0] = fma2(w2, xv.x, acc[i][0]);
                acc[i][1] = fma2(w2, xv.y, acc[i][1]);
            }
        }
        __syncthreads();
    }
    #pragma unroll
    for (int i = 0; i < 8; i++) {
        int row = rt * 128 + ty * 8 + i;
        float bi = bias[row];
        ull bpr = pk2(bi, bi);
        ull* gp = (ull*)&g_gates2[(size_t)(t * G4H + row) * BB];
        gp[tx * 2]     = add2(acc[i][0], bpr);
        gp[tx * 2 + 1] = add2(acc[i][1], bpr);
    }
}

// steal loop over 4096 units (t,rt); unit ready when g_gen >= 2t+2
__device__ void steal_loop(int tid, char* smraw,
                           const float* __restrict__ W, const float* __restrict__ bias) {
    __shared__ int sTk;
    for (;;) {
        __syncthreads();
        if (tid == 0) sTk = (int)atomicAdd(&g_ticket, 1u);
        __syncthreads();
        int tk = sTk;
        if (tk >= TT * 16) break;
        int t = tk >> 4, rt = tk & 15;
        if (tid == 0) {
            unsigned need = 2u * t + 2u;
            while (g_gen < need) { }
            __threadfence();
        }
        __syncthreads();
        gemm_unit(t, rt, tid, smraw, W, bias);
    }
}

// ---------------- fused kernel A: scan1 (blocks 0..127) + gemm workers ----------------
__global__ __launch_bounds__(NTS, 1)
void scanA_kernel(const float* __restrict__ sent,
                  const float* __restrict__ W_ih, const float* __restrict__ W_hh,
                  const float* __restrict__ b_cell,
                  const float* __restrict__ W1, const float* __restrict__ b1,
                  const float* __restrict__ W_ihl, const float* __restrict__ b_l) {
    extern __shared__ __align__(16) char smraw[];
    int tid = threadIdx.x;

    if (blockIdx.x < NB) {
        ull*   wS2  = (ull*)smraw;                    // [XD][16] pairs {w,w}
        float* xS   = (float*)(wS2 + 16 * XD);        // double buffer 2 x [128][128]
        float* gS   = xS + 2 * 16384;                 // [16][128]
        float* hb   = gS + 16 * BB;                   // 512
        float* ipS  = hb + HH;                        // 32
        float* pS   = ipS + 32;                       // 32
        float* phiS = pS + 32;                        // 64
        ull*   part = (ull*)(xS + 16384);             // buf1 (last tile uses buf0)

        int b   = blockIdx.x;
        int hu0 = b * 4;
        int bg = tid & 7, rg = (tid >> 3) & 7, kc = tid >> 6;
        int lane = tid & 31, wid = tid >> 5;

        for (int i = tid; i < 16 * XD; i += NTS) {
            int k = i >> 4, r = i & 15;
            int g4 = r & 3, hl = r >> 2;
            int grow = g4 * HH + hu0 + hl;
            float w = (k < XD1) ? W_ih[grow * XD1 + k] : W_hh[grow * HH + (k - XD1)];
            wS2[i] = pk2(w, w);
        }
        int prow0 = tid >> 6, prow1 = prow0 + 8;
        int bp = tid & 63;
        float bias0 = b_cell[(prow0 & 3) * HH + hu0 + (prow0 >> 2)];
        float bias1 = b_cell[(prow1 & 3) * HH + hu0 + (prow1 >> 2)];
        ull bpr0 = pk2(bias0, bias0), bpr1 = pk2(bias1, bias1);
        __syncthreads();

        for (int t = 0; t < TT; t++) {
            // ---- phase A: attention window for batch b (W1 from L2) ----
            if (tid < HH) hb[tid] = g_h1[b * HH + tid];
            __syncthreads();
            for (int j = wid; j < 3 * KK; j += 16) {
                float s = 0.0f;
                const float* w1r = W1 + j * HH;
                #pragma unroll
                for (int m = 0; m < 16; m++) {
                    int id = lane + 32 * m;
                    s += hb[id] * w1r[id];
                }
                for (int o = 16; o > 0; o >>= 1) s += __shfl_down_sync(0xffffffffu, s, o);
                if (lane == 0) ipS[j] = expf(s + b1[j]);
            }
            __syncthreads();
            if (tid < 3 * KK) {
                float pn = ipS[tid];
                if (tid >= 2 * KK) pn -= g_p[b * 3 * KK + tid];
                g_p[b * 3 * KK + tid] = pn;
                pS[tid] = pn;
            }
            __syncthreads();
            if (tid < SS) {
                float u = (float)(tid + 1);
                float s = 0.0f;
                #pragma unroll
                for (int k = 0; k < KK; k++) {
                    float d = pS[2 * KK + k] - u;
                    s += pS[k] * expf(-pS[KK + k] * d * d);
                }
                phiS[tid] = s;
            }
            __syncthreads();
            if (tid < CSLN) {
                float s = 0.0f;
                const float* sb = sent + b * SS * CSLN + tid;
                #pragma unroll 8
                for (int ss = 0; ss < SS; ss++) s += phiS[ss] * sb[ss * CSLN];
                g_winT[(t * CSLN + tid) * BB + b] = s;
            }
            gbar();

            // ---- phase B: gates [16 x 128], K=575, double-buffered tiles ----
            const float* h1rd = g_h1T[t & 1];
            ull acc[2][8];
            #pragma unroll
            for (int r = 0; r < 2; r++)
                #pragma unroll
                for (int j = 0; j < 8; j++) acc[r][j] = 0ull;

            float pf[32];
            #pragma unroll
            for (int j = 0; j < 32; j++) {
                int e = tid + j * NTS;
                pf[j] = fetch1(t, e >> 7, e & 127, h1rd);
            }
            for (int tile = 0; tile < 5; tile++) {
                int kbase = tile * 128;
                int ks = (tile == 4) ? (XD - 512) : 128;
                float* bufc = xS + (tile & 1) * 16384;
                #pragma unroll
                for (int j = 0; j < 32; j++) {
                    int e = tid + j * NTS;
                    if (e < ks * 128) bufc[e] = pf[j];
                }
                __syncthreads();
                if (tile < 4) {
                    int kb2 = kbase + 128;
                    int ks2 = (tile == 3) ? (XD - 512) : 128;
                    #pragma unroll
                    for (int j = 0; j < 32; j++) {
                        int e = tid + j * NTS;
                        if (e < ks2 * 128) pf[j] = fetch1(t, kb2 + (e >> 7), e & 127, h1rd);
                    }
                }
                int k0 = kc * 16;
                int k1 = min(ks, k0 + 16);
                for (int kk = k0; kk < k1; kk++) {
                    ulonglong2 wv = *(const ulonglong2*)&wS2[(kbase + kk) * 16 + rg * 2];
                    ulonglong2 xa = *(const ulonglong2*)&bufc[kk * 128 + bg * 4];
                    ulonglong2 xb = *(const ulonglong2*)&bufc[kk * 128 + 32 + bg * 4];
                    ulonglong2 xc = *(const ulonglong2*)&bufc[kk * 128 + 64 + bg * 4];
                    ulonglong2 xd = *(const ulonglong2*)&bufc[kk * 128 + 96 + bg * 4];
                    acc[0][0] = fma2(wv.x, xa.x, acc[0][0]);
                    acc[0][1] = fma2(wv.x, xa.y, acc[0][1]);
                    acc[0][2] = fma2(wv.x, xb.x, acc[0][2]);
                    acc[0][3] = fma2(wv.x, xb.y, acc[0][3]);
                    acc[0][4] = fma2(wv.x, xc.x, acc[0][4]);
                    acc[0][5] = fma2(wv.x, xc.y, acc[0][5]);
                    acc[0][6] = fma2(wv.x, xd.x, acc[0][6]);
                    acc[0][7] = fma2(wv.x, xd.y, acc[0][7]);
                    acc[1][0] = fma2(wv.y, xa.x, acc[1][0]);
                    acc[1][1] = fma2(wv.y, xa.y, acc[1][1]);
                    acc[1][2] = fma2(wv.y, xb.x, acc[1][2]);
                    acc[1][3] = fma2(wv.y, xb.y, acc[1][3]);
                    acc[1][4] = fma2(wv.y, xc.x, acc[1][4]);
                    acc[1][5] = fma2(wv.y, xc.y, acc[1][5]);
                    acc[1][6] = fma2(wv.y, xd.x, acc[1][6]);
                    acc[1][7] = fma2(wv.y, xd.y, acc[1][7]);
                }
            }
            __syncthreads();
            #pragma unroll
            for (int r = 0; r < 2; r++)
                #pragma unroll
                for (int j = 0; j < 8; j++)
                    part[(kc * 16 + rg * 2 + r) * 64 + (j >> 1) * 16 + bg * 2 + (j & 1)] = acc[r][j];
            __syncthreads();
            {
                ull s0 = bpr0, s1 = bpr1;
                #pragma unroll
                for (int q = 0; q < 8; q++) {
                    s0 = add2(s0, part[(q * 16 + prow0) * 64 + bp]);
                    s1 = add2(s1, part[(q * 16 + prow1) * 64 + bp]);
                }
                ((ull*)gS)[prow0 * 64 + bp] = s0;
                ((ull*)gS)[prow1 * 64 + bp] = s1;
            }
            __syncthreads();
            {
                float* h1wr = g_h1T[(t + 1) & 1];
                int hl = tid >> 7, bb2 = tid & 127;
                int hu = hu0 + hl;
                float gi = sigf(gS[(hl * 4 + 0) * BB + bb2]);
                float gf = sigf(gS[(hl * 4 + 1) * BB + bb2]);
                float gg = tanhf(gS[(hl * 4 + 2) * BB + bb2]);
                float go = sigf(gS[(hl * 4 + 3) * BB + bb2]);
                float c = gf * g_c1T[hu * BB + bb2] + gi * gg;
                float h = go * tanhf(c);
                g_c1T[hu * BB + bb2] = c;
                h1wr[hu * BB + bb2] = h;
                g_h1[bb2 * HH + hu] = h;
                g_h1seqT[(t * HH + hu) * BB + bb2] = h;
            }
            gbar();
        }
    }
    // everyone (scan blocks after finishing, worker blocks immediately) drains the gemm queue
    steal_loop(tid, smraw, W_ihl, b_l);
}

// ---------------- scan 2: second LSTM ----------------
__global__ __launch_bounds__(NTS, 1)
void scan2_kernel(const float* __restrict__ W_hh_l) {
    extern __shared__ __align__(16) char smraw[];
    ull*   wS2 = (ull*)smraw;              // [512][16] pairs
    float* xS  = (float*)(wS2 + 16 * HH);  // double buffer 2 x [128][128]
    float* gS  = xS + 2 * 16384;           // [16][128]
    ull*   part = (ull*)xS;                // buf0 (last tile uses buf1)

    int tid = threadIdx.x;
    int hu0 = blockIdx.x * 4;
    int bg = tid & 7, rg = (tid >> 3) & 7, kc = tid >> 6;

    for (int i = tid; i < 16 * HH; i += NTS) {
        int k = i >> 4, r = i & 15;
        int g4 = r & 3, hl = r >> 2;
        float w = W_hh_l[(g4 * HH + hu0 + hl) * HH + k];
        wS2[i] = pk2(w, w);
    }
    int prow0 = tid >> 6, prow1 = prow0 + 8;
    int bp = tid & 63;
    int grow0 = (prow0 & 3) * HH + hu0 + (prow0 >> 2);
    int grow1 = (prow1 & 3) * HH + hu0 + (prow1 >> 2);
    __syncthreads();

    for (int t = 0; t < TT; t++) {
        const float* hrd = g_h2T[t & 1];
        ull acc[2][8];
        #pragma unroll
        for (int r = 0; r < 2; r++)
            #pragma unroll
            for (int j = 0; j < 8; j++) acc[r][j] = 0ull;

        float pf[32];
        #pragma unroll
        for (int j = 0; j < 32; j++) pf[j] = hrd[tid + j * NTS];
        for (int tile = 0; tile < 4; tile++) {
            float* bufc = xS + (tile & 1) * 16384;
            #pragma unroll
            for (int j = 0; j < 32; j++) bufc[tid + j * NTS] = pf[j];
            __syncthreads();
            if (tile < 3) {
                const float* src = hrd + (tile + 1) * 128 * 128;
                #pragma unroll
                for (int j = 0; j < 32; j++) pf[j] = src[tid + j * NTS];
            }
            int kbase = tile * 128;
            int k0 = kc * 16;
            #pragma unroll 2
            for (int kk = k0; kk < k0 + 16; kk++) {
                ulonglong2 wv = *(const ulonglong2*)&wS2[(kbase + kk) * 16 + rg * 2];
                ulonglong2 xa = *(const ulonglong2*)&bufc[kk * 128 + bg * 4];
                ulonglong2 xb = *(const ulonglong2*)&bufc[kk * 128 + 32 + bg * 4];
                ulonglong2 xc = *(const ulonglong2*)&bufc[kk * 128 + 64 + bg * 4];
                ulonglong2 xd = *(const ulonglong2*)&bufc[kk * 128 + 96 + bg * 4];
                acc[0][0] = fma2(wv.x, xa.x, acc[0][0]);
                acc[0][1] = fma2(wv.x, xa.y, acc[0][1]);
                acc[0][2] = fma2(wv.x, xb.x, acc[0][2]);
                acc[0][3] = fma2(wv.x, xb.y, acc[0][3]);
                acc[0][4] = fma2(wv.x, xc.x, acc[0][4]);
                acc[0][5] = fma2(wv.x, xc.y, acc[0][5]);
                acc[0][6] = fma2(wv.x, xd.x, acc[0][6]);
                acc[0][7] = fma2(wv.x, xd.y, acc[0][7]);
                acc[1][0] = fma2(wv.y, xa.x, acc[1][0]);
                acc[1][1] = fma2(wv.y, xa.y, acc[1][1]);
                acc[1][2] = fma2(wv.y, xb.x, acc[1][2]);
                acc[1][3] = fma2(wv.y, xb.y, acc[1][3]);
                acc[1][4] = fma2(wv.y, xc.x, acc[1][4]);
                acc[1][5] = fma2(wv.y, xc.y, acc[1][5]);
                acc[1][6] = fma2(wv.y, xd.x, acc[1][6]);
                acc[1][7] = fma2(wv.y, xd.y, acc[1][7]);
            }
        }
        __syncthreads();
        #pragma unroll
        for (int r = 0; r < 2; r++)
            #pragma unroll
            for (int j = 0; j < 8; j++)
                part[(kc * 16 + rg * 2 + r) * 64 + (j >> 1) * 16 + bg * 2 + (j & 1)] = acc[r][j];
        __syncthreads();
        {
            const ull* pre0 = (const ull*)&g_gates2[(size_t)(t * G4H + grow0) * BB];
            const ull* pre1 = (const ull*)&g_gates2[(size_t)(t * G4H + grow1) * BB];
            ull s0 = pre0[bp], s1 = pre1[bp];
            #pragma unroll
            for (int q = 0; q < 8; q++) {
                s0 = add2(s0, part[(q * 16 + prow0) * 64 + bp]);
                s1 = add2(s1, part[(q * 16 + prow1) * 64 + bp]);
            }
            ((ull*)gS)[prow0 * 64 + bp] = s0;
            ((ull*)gS)[prow1 * 64 + bp] = s1;
        }
        __syncthreads();
        {
            float* hwr = g_h2T[(t + 1) & 1];
            int hl = tid >> 7, bb2 = tid & 127;
            int hu = hu0 + hl;
            float gi = sigf(gS[(hl * 4 + 0) * BB + bb2]);
            float gf = sigf(gS[(hl * 4 + 1) * BB + bb2]);
            float gg = tanhf(gS[(hl * 4 + 2) * BB + bb2]);
            float go = sigf(gS[(hl * 4 + 3) * BB + bb2]);
            float c = gf * g_c2T[hu * BB + bb2] + gi * gg;
            float h = go * tanhf(c);
            g_c2T[hu * BB + bb2] = c;
            hwr[hu * BB + bb2] = h;
            g_yT[(t * HH + hu) * BB + bb2] = h;
        }
        gbar();
    }
}

// ---------------- final projection ----------------
__global__ void final_kernel(const float* __restrict__ W2, const float* __restrict__ b2,
                             float* __restrict__ out) {
    __shared__ float w_s[128 * 33];
    __shared__ float y_s[32 * 128];
    int t = blockIdx.x;
    int tid = threadIdx.x, tx = tid & 15, ty = tid >> 4;
    int lk = tid & 31, lo0 = tid >> 5;
    int lb = tid & 127, lq = tid >> 7;

    float acc[8][8];
    #pragma unroll
    for (int i = 0; i < 8; i++)
        #pragma unroll
        for (int j = 0; j < 8; j++) acc[i][j] = 0.0f;

    for (int k0 = 0; k0 < HH; k0 += 32) {
        for (int oo = lo0; oo < 128; oo += 8)
            w_s[oo * 33 + lk] = (oo < DOUT) ? W2[oo * HH + k0 + lk] : 0.0f;
        for (int kk = lq; kk < 32; kk += 2)
            y_s[kk * BB + lb] = g_yT[(t * HH + k0 + kk) * BB + lb];
        __syncthreads();
        for (int kk = 0; kk < 32; kk++) {
            float wf[8];
            #pragma unroll
            for (int i = 0; i < 8; i++) wf[i] = w_s[(ty * 8 + i) * 33 + kk];
            float4 xa = *(const float4*)&y_s[kk * 128 + tx * 4];
            float4 xb = *(const float4*)&y_s[kk * 128 + 64 + tx * 4];
            float xf[8] = {xa.x, xa.y, xa.z, xa.w, xb.x, xb.y, xb.z, xb.w};
            #pragma unroll
            for (int i = 0; i < 8; i++)
                #pragma unroll
                for (int j = 0; j < 8; j++) acc[i][j] += wf[i] * xf[j];
        }
        __syncthreads();
    }
    #pragma unroll
    for (int i = 0; i < 8; i++) {
        int o = ty * 8 + i;
        if (o < DOUT) {
            float bi = b2[o];
            #pragma unroll
            for (int j = 0; j < 8; j++) {
                int bb2 = (j >> 2) * 64 + tx * 4 + (j & 3);
                out[(size_t)(bb2 * TT + t) * DOUT + o] = acc[i][j] + bi;
            }
        }
    }
}

// ---------------- epilogue ----------------
__global__ void epi_kernel(float* __restrict__ out) {
    int idx = blockIdx.x * blockDim.x + threadIdx.x;
    if (idx >= BB * HH) return;
    int b = idx / HH, h = idx % HH;
    size_t base = (size_t)BB * TT * DOUT;
    out[base + idx]               = g_h1[idx];
    out[base + BB * HH + idx]     = g_c1T[h * BB + b];
    out[base + 2 * BB * HH + idx] = g_h2T[0][h * BB + b];
    out[base + 3 * BB * HH + idx] = g_c2T[h * BB + b];
}

extern "C" void kernel_launch(void* const* d_in, const int* in_sizes, int n_in,
                              void* d_out, int out_size) {
    const float* x      = (const float*)d_in[0];
    const float* sent   = (const float*)d_in[1];
    const float* h1h    = (const float*)d_in[2];
    const float* h1c    = (const float*)d_in[3];
    const float* h2h    = (const float*)d_in[4];
    const float* h2c    = (const float*)d_in[5];
    const float* Wihc   = (const float*)d_in[6];
    const float* Whhc   = (const float*)d_in[7];
    const float* bcell  = (const float*)d_in[8];
    const float* Wihl   = (const float*)d_in[9];
    const float* Whhl   = (const float*)d_in[10];
    const float* bl     = (const float*)d_in[11];
    const float* W1     = (const float*)d_in[12];
    const float* b1     = (const float*)d_in[13];
    const float* W2     = (const float*)d_in[14];
    const float* b2     = (const float*)d_in[15];
    float* out = (float*)d_out;

    // scanA: wS2 73600 + xS 131072 + gS 8192 + hb 2048 + misc 512 = 215424 B
    size_t smA = (size_t)16 * XD * 8 + 2 * 16384 * 4 + 16 * BB * 4 + HH * 4 + 128 * 4;
    // scan2: wS2 65536 + xS 131072 + gS 8192 = 204800 B
    size_t sm2 = (size_t)16 * HH * 8 + 2 * 16384 * 4 + 16 * BB * 4;
    cudaFuncSetAttribute(scanA_kernel, cudaFuncAttributeMaxDynamicSharedMemorySize, (int)smA);
    cudaFuncSetAttribute(scan2_kernel, cudaFuncAttributeMaxDynamicSharedMemorySize, (int)sm2);

    int init_n = BB * HH + BB * 3 * KK + TT * DIN * BB;
    init_kernel<<<(init_n + 255) / 256, 256>>>(x, h1h, h1c, h2h, h2c);
    scanA_kernel<<<NBA, NTS, smA>>>(sent, Wihc, Whhc, bcell, W1, b1, Wihl, bl);
    scan2_kernel<<<NB, NTS, sm2>>>(Whhl);
    final_kernel<<<TT, 256>>>(W2, b2, out);
    epi_kernel<<<(BB * HH + 255) / 256, 256>>>(out);
}

// round 7
// speedup vs baseline: 3.6617x; 1.0192x over previous
#include <cuda_runtime.h>
#include <cuda_bf16.h>
#include <math.h>

#define BB   128
#define TT   256
#define SS   64
#define DIN  3
#define HH   512
#define KK   10
#define CSLN 60
#define DOUT 121
#define G4H  2048
#define XD   575   // DIN + CSLN + HH (gemm order: x,win,h)
#define XD1  63    // DIN + CSLN
#define XDP  576   // scan1 permuted+padded: [h 512 | x 3 | win 60 | zero 1]

#define NB   128   // scan blocks (barrier count)
#define NBA  148   // total blocks in fused kernel (all resident)
#define NTS  512

typedef unsigned long long ull;

__device__ __forceinline__ ull pk2(float lo, float hi) {
    ull r; asm("mov.b64 %0,{%1,%2};" : "=l"(r) : "f"(lo), "f"(hi)); return r;
}
__device__ __forceinline__ ull fma2(ull a, ull b, ull c) {
    ull d; asm("fma.rn.f32x2 %0,%1,%2,%3;" : "=l"(d) : "l"(a), "l"(b), "l"(c)); return d;
}
__device__ __forceinline__ ull add2(ull a, ull b) {
    ull d; asm("add.rn.f32x2 %0,%1,%2;" : "=l"(d) : "l"(a), "l"(b)); return d;
}

// ---------------- device scratch ----------------
__device__ __align__(16) float g_h1[BB * HH];
__device__ __align__(16) float g_h1T[2][HH * BB];
__device__ __align__(16) float g_c1T[HH * BB];
__device__ __align__(16) float g_h2T[2][HH * BB];
__device__ __align__(16) float g_c2T[HH * BB];
__device__ __align__(16) float g_p[BB * 3 * KK];
__device__ __align__(16) float g_xw[TT * 64 * BB];   // [t][64 rows: x0..2,win0..59,zero][b]
__device__ __align__(16) float g_h1seqT[TT * HH * BB];
__device__ __align__(16) float g_gates2[TT * G4H * BB];
__device__ __align__(16) float g_yT[TT * HH * BB];
__device__ unsigned g_cnt = 0;
__device__ volatile unsigned g_gen = 0;
__device__ unsigned g_ticket = 0;

__device__ __forceinline__ float sigf(float x) { return 1.0f / (1.0f + expf(-x)); }

// barrier across the NB scan blocks only
__device__ __forceinline__ void gbar() {
    __syncthreads();
    if (threadIdx.x == 0) {
        unsigned gen = g_gen;
        __threadfence();
        if (atomicAdd(&g_cnt, 1) == NB - 1) {
            g_cnt = 0;
            __threadfence();
            g_gen = gen + 1;
        } else {
            while (g_gen == gen) { }
        }
    }
    __syncthreads();
}

// ---------------- init ----------------
__global__ void init_kernel(const float* __restrict__ x,
                            const float* __restrict__ h1h, const float* __restrict__ h1c,
                            const float* __restrict__ h2h, const float* __restrict__ h2c) {
    int idx = blockIdx.x * blockDim.x + threadIdx.x;
    if (idx == 0) { g_cnt = 0; g_gen = 0; g_ticket = 0; }
    if (idx < BB * HH) {
        int b = idx / HH, h = idx % HH;
        float v = h1h[idx];
        g_h1[idx] = v;
        g_h1T[0][h * BB + b] = v;
        g_c1T[h * BB + b] = h1c[idx];
        g_h2T[0][h * BB + b] = h2h[idx];
        g_c2T[h * BB + b] = h2c[idx];
    }
    int i2 = idx - BB * HH;
    if (i2 >= 0 && i2 < BB * 3 * KK) g_p[i2] = 0.0f;
    int i3 = idx - BB * HH - BB * 3 * KK;
    if (i3 >= 0 && i3 < TT * DIN * BB) {
        int b = i3 % BB;
        int r = i3 / BB;
        int t = r / DIN, i = r % DIN;
        g_xw[(t * 64 + i) * BB + b] = x[(b * TT + t) * DIN + i];
    }
    int i4 = i3 - TT * DIN * BB;
    if (i4 >= 0 && i4 < TT * BB) {
        int t = i4 / BB, b = i4 % BB;
        g_xw[(t * 64 + 63) * BB + b] = 0.0f;
    }
}

// gemm feature fetch (original order): kg in [0,XD)
__device__ __forceinline__ float fetch_seq(int t, int kg, int bb) {
    if (kg < XD1) return g_xw[(t * 64 + kg) * BB + bb];
    else          return g_h1seqT[(t * HH + (kg - XD1)) * BB + bb];
}

// ---------------- gemm work unit: gates2[t] rows [rt*128, rt*128+128) ----------------
__device__ void gemm_unit(int t, int rt, int tid, char* smraw,
                          const float* __restrict__ W, const float* __restrict__ bias) {
    ull*   a_s = (ull*)smraw;               // [128][33] pairs {w,w}
    float* x_s = (float*)(a_s + 128 * 33);  // [32][128]
    int ty = tid >> 5, tx = tid & 31;

    ull acc[8][2];
    #pragma unroll
    for (int i = 0; i < 8; i++) { acc[i][0] = 0ull; acc[i][1] = 0ull; }

    for (int k0 = 0; k0 < XD; k0 += 32) {
        for (int i = tid; i < 128 * 32; i += NTS) {
            int row = i >> 5, kk = i & 31;
            int k = k0 + kk;
            float w = (k < XD) ? W[(rt * 128 + row) * XD + k] : 0.0f;
            a_s[row * 33 + kk] = pk2(w, w);
        }
        for (int i = tid; i < 32 * 128; i += NTS) {
            int kk = i >> 7, bb = i & 127;
            int k = k0 + kk;
            x_s[i] = (k < XD) ? fetch_seq(t, k, bb) : 0.0f;
        }
        __syncthreads();
        #pragma unroll 4
        for (int kk = 0; kk < 32; kk++) {
            ulonglong2 xv = *(const ulonglong2*)&x_s[kk * 128 + tx * 4];
            #pragma unroll
            for (int i = 0; i < 8; i++) {
                ull w2 = a_s[(ty * 8 + i) * 33 + kk];
                acc[i][0] = fma2(w2, xv.x, acc[i][0]);
                acc[i][1] = fma2(w2, xv.y, acc[i][1]);
            }
        }
        __syncthreads();
    }
    #pragma unroll
    for (int i = 0; i < 8; i++) {
        int row = rt * 128 + ty * 8 + i;
        float bi = bias[row];
        ull bpr = pk2(bi, bi);
        ull* gp = (ull*)&g_gates2[(size_t)(t * G4H + row) * BB];
        gp[tx * 2]     = add2(acc[i][0], bpr);
        gp[tx * 2 + 1] = add2(acc[i][1], bpr);
    }
}

__device__ void steal_loop(int tid, char* smraw,
                           const float* __restrict__ W, const float* __restrict__ bias) {
    __shared__ int sTk;
    for (;;) {
        __syncthreads();
        if (tid == 0) sTk = (int)atomicAdd(&g_ticket, 1u);
        __syncthreads();
        int tk = sTk;
        if (tk >= TT * 16) break;
        int t = tk >> 4, rt = tk & 15;
        if (tid == 0) {
            unsigned need = 2u * t + 2u;
            while (g_gen < need) { }
            __threadfence();
        }
        __syncthreads();
        gemm_unit(t, rt, tid, smraw, W, bias);
    }
}

// ---------------- fused kernel A: scan1 + gemm workers ----------------
__global__ __launch_bounds__(NTS, 1)
void scanA_kernel(const float* __restrict__ sent,
                  const float* __restrict__ W_ih, const float* __restrict__ W_hh,
                  const float* __restrict__ b_cell,
                  const float* __restrict__ W1, const float* __restrict__ b1,
                  const float* __restrict__ W_ihl, const float* __restrict__ b_l) {
    extern __shared__ __align__(16) char smraw[];
    int tid = threadIdx.x;

    if (blockIdx.x < NB) {
        ull*   wS2  = (ull*)smraw;                    // [XDP][16] pairs {w,w}
        float* xS   = (float*)(wS2 + 16 * XDP);       // 2 x [64][128] double buffer
        float* gS   = xS + 2 * 8192;                  // [16][128]
        float* hb   = gS + 16 * BB;                   // 512
        float* ipS  = hb + HH;                        // 32
        float* pS   = ipS + 32;                       // 32
        float* phiS = pS + 32;                        // 64
        ull*   part = (ull*)xS;                       // 64KB = both buffers

        int b   = blockIdx.x;
        int hu0 = b * 4;
        int bg = tid & 7, rg = (tid >> 3) & 7, kc = tid >> 6;
        int lane = tid & 31, wid = tid >> 5;
        int rot = b & 7;

        // permuted weights: k<512 -> W_hh col k; k>=512 -> W_ih col (k-512); k=575 pad 0
        for (int i = tid; i < 16 * XDP; i += NTS) {
            int k = i >> 4, r = i & 15;
            int g4 = r & 3, hl = r >> 2;
            int grow = g4 * HH + hu0 + hl;
            float w;
            if (k < HH) w = W_hh[grow * HH + k];
            else { int j = k - HH; w = (j < XD1) ? W_ih[grow * XD1 + j] : 0.0f; }
            wS2[i] = pk2(w, w);
        }
        int prow0 = tid >> 6, prow1 = prow0 + 8;
        int bp = tid & 63;
        float bias0 = b_cell[(prow0 & 3) * HH + hu0 + (prow0 >> 2)];
        float bias1 = b_cell[(prow1 & 3) * HH + hu0 + (prow1 >> 2)];
        ull bpr0 = pk2(bias0, bias0), bpr1 = pk2(bias1, bias1);
        __syncthreads();

        for (int t = 0; t < TT; t++) {
            // ---- phase A: attention window for batch b ----
            if (tid < HH) hb[tid] = g_h1[b * HH + tid];
            __syncthreads();
            for (int j = wid; j < 3 * KK; j += 16) {
                float s = 0.0f;
                const float* w1r = W1 + j * HH;
                #pragma unroll
                for (int m = 0; m < 16; m++) {
                    int id = lane + 32 * m;
                    s += hb[id] * w1r[id];
                }
                for (int o = 16; o > 0; o >>= 1) s += __shfl_down_sync(0xffffffffu, s, o);
                if (lane == 0) ipS[j] = expf(s + b1[j]);
            }
            __syncthreads();
            if (tid < 3 * KK) {
                float pn = ipS[tid];
                if (tid >= 2 * KK) pn -= g_p[b * 3 * KK + tid];
                g_p[b * 3 * KK + tid] = pn;
                pS[tid] = pn;
            }
            __syncthreads();
            if (tid < SS) {
                float u = (float)(tid + 1);
                float s = 0.0f;
                #pragma unroll
                for (int k = 0; k < KK; k++) {
                    float d = pS[2 * KK + k] - u;
                    s += pS[k] * expf(-pS[KK + k] * d * d);
                }
                phiS[tid] = s;
            }
            __syncthreads();
            if (tid < CSLN) {
                float s = 0.0f;
                const float* sb = sent + b * SS * CSLN + tid;
                #pragma unroll 8
                for (int ss = 0; ss < SS; ss++) s += phiS[ss] * sb[ss * CSLN];
                g_xw[(t * 64 + DIN + tid) * BB + b] = s;
            }
            gbar();

            // ---- phase B: gates [16 x 128], 9 uniform 64-k tiles, reg->STS staging ----
            const float* h1rd = g_h1T[t & 1];
            const float* xwsrc = g_xw + t * 8192;
            ull acc[2][8];
            #pragma unroll
            for (int r = 0; r < 2; r++)
                #pragma unroll
                for (int j = 0; j < 8; j++) acc[r][j] = 0ull;

            float4 pf[4];
            {
                const float* s0 = h1rd + rot * 8192;
                #pragma unroll
                for (int q = 0; q < 4; q++) pf[q] = *(const float4*)(s0 + q * 2048 + tid * 4);
            }
            for (int i = 0; i < 9; i++) {
                float* bufc = xS + (i & 1) * 8192;
                #pragma unroll
                for (int q = 0; q < 4; q++) *(float4*)(bufc + q * 2048 + tid * 4) = pf[q];
                __syncthreads();
                if (i < 8) {
                    const float* sn = (i + 1 < 8) ? (h1rd + (((i + 1 + rot) & 7) * 8192))
                                                  : xwsrc;
                    #pragma unroll
                    for (int q = 0; q < 4; q++) pf[q] = *(const float4*)(sn + q * 2048 + tid * 4);
                }
                int kb = (i < 8) ? (((i + rot) & 7) * 64) : HH;
                #pragma unroll
                for (int kq = 0; kq < 8; kq++) {
                    int kk = kc * 8 + kq;
                    ulonglong2 wv = *(const ulonglong2*)&wS2[(kb + kk) * 16 + rg * 2];
                    ulonglong2 xa = *(const ulonglong2*)&bufc[kk * 128 + bg * 4];
                    ulonglong2 xb = *(const ulonglong2*)&bufc[kk * 128 + 32 + bg * 4];
                    ulonglong2 xc = *(const ulonglong2*)&bufc[kk * 128 + 64 + bg * 4];
                    ulonglong2 xd = *(const ulonglong2*)&bufc[kk * 128 + 96 + bg * 4];
                    acc[0][0] = fma2(wv.x, xa.x, acc[0][0]);
                    acc[0][1] = fma2(wv.x, xa.y, acc[0][1]);
                    acc[0][2] = fma2(wv.x, xb.x, acc[0][2]);
                    acc[0][3] = fma2(wv.x, xb.y, acc[0][3]);
                    acc[0][4] = fma2(wv.x, xc.x, acc[0][4]);
                    acc[0][5] = fma2(wv.x, xc.y, acc[0][5]);
                    acc[0][6] = fma2(wv.x, xd.x, acc[0][6]);
                    acc[0][7] = fma2(wv.x, xd.y, acc[0][7]);
                    acc[1][0] = fma2(wv.y, xa.x, acc[1][0]);
                    acc[1][1] = fma2(wv.y, xa.y, acc[1][1]);
                    acc[1][2] = fma2(wv.y, xb.x, acc[1][2]);
                    acc[1][3] = fma2(wv.y, xb.y, acc[1][3]);
                    acc[1][4] = fma2(wv.y, xc.x, acc[1][4]);
                    acc[1][5] = fma2(wv.y, xc.y, acc[1][5]);
                    acc[1][6] = fma2(wv.y, xd.x, acc[1][6]);
                    acc[1][7] = fma2(wv.y, xd.y, acc[1][7]);
                }
                __syncthreads();
            }
            #pragma unroll
            for (int r = 0; r < 2; r++)
                #pragma unroll
                for (int j = 0; j < 8; j++)
                    part[(kc * 16 + rg * 2 + r) * 64 + (j >> 1) * 16 + bg * 2 + (j & 1)] = acc[r][j];
            __syncthreads();
            {
                ull s0 = bpr0, s1 = bpr1;
                #pragma unroll
                for (int q = 0; q < 8; q++) {
                    s0 = add2(s0, part[(q * 16 + prow0) * 64 + bp]);
                    s1 = add2(s1, part[(q * 16 + prow1) * 64 + bp]);
                }
                ((ull*)gS)[prow0 * 64 + bp] = s0;
                ((ull*)gS)[prow1 * 64 + bp] = s1;
            }
            __syncthreads();
            {
                float* h1wr = g_h1T[(t + 1) & 1];
                int hl = tid >> 7, bb2 = tid & 127;
                int hu = hu0 + hl;
                float gi = sigf(gS[(hl * 4 + 0) * BB + bb2]);
                float gf = sigf(gS[(hl * 4 + 1) * BB + bb2]);
                float gg = tanhf(gS[(hl * 4 + 2) * BB + bb2]);
                float go = sigf(gS[(hl * 4 + 3) * BB + bb2]);
                float c = gf * g_c1T[hu * BB + bb2] + gi * gg;
                float h = go * tanhf(c);
                g_c1T[hu * BB + bb2] = c;
                h1wr[hu * BB + bb2] = h;
                g_h1[bb2 * HH + hu] = h;
                g_h1seqT[(t * HH + hu) * BB + bb2] = h;
            }
            gbar();
        }
    }
    steal_loop(tid, smraw, W_ihl, b_l);
}

// ---------------- scan 2: second LSTM ----------------
__global__ __launch_bounds__(NTS, 1)
void scan2_kernel(const float* __restrict__ W_hh_l) {
    extern __shared__ __align__(16) char smraw[];
    ull*   wS2 = (ull*)smraw;              // [512][16] pairs
    float* xS  = (float*)(wS2 + 16 * HH);  // 2 x [64][128] double buffer
    float* gS  = xS + 2 * 8192;            // [16][128]
    ull*   part = (ull*)xS;                // both buffers

    int tid = threadIdx.x;
    int hu0 = blockIdx.x * 4;
    int bg = tid & 7, rg = (tid >> 3) & 7, kc = tid >> 6;
    int rot = blockIdx.x & 7;

    for (int i = tid; i < 16 * HH; i += NTS) {
        int k = i >> 4, r = i & 15;
        int g4 = r & 3, hl = r >> 2;
        float w = W_hh_l[(g4 * HH + hu0 + hl) * HH + k];
        wS2[i] = pk2(w, w);
    }
    int prow0 = tid >> 6, prow1 = prow0 + 8;
    int bp = tid & 63;
    int grow0 = (prow0 & 3) * HH + hu0 + (prow0 >> 2);
    int grow1 = (prow1 & 3) * HH + hu0 + (prow1 >> 2);
    __syncthreads();

    for (int t = 0; t < TT; t++) {
        const float* hrd = g_h2T[t & 1];
        ull acc[2][8];
        #pragma unroll
        for (int r = 0; r < 2; r++)
            #pragma unroll
            for (int j = 0; j < 8; j++) acc[r][j] = 0ull;

        float4 pf[4];
        {
            const float* s0 = hrd + rot * 8192;
            #pragma unroll
            for (int q = 0; q < 4; q++) pf[q] = *(const float4*)(s0 + q * 2048 + tid * 4);
        }
        for (int i = 0; i < 8; i++) {
            float* bufc = xS + (i & 1) * 8192;
            #pragma unroll
            for (int q = 0; q < 4; q++) *(float4*)(bufc + q * 2048 + tid * 4) = pf[q];
            __syncthreads();
            if (i < 7) {
                const float* sn = hrd + (((i + 1 + rot) & 7) * 8192);
                #pragma unroll
                for (int q = 0; q < 4; q++) pf[q] = *(const float4*)(sn + q * 2048 + tid * 4);
            }
            int kb = ((i + rot) & 7) * 64;
            #pragma unroll
            for (int kq = 0; kq < 8; kq++) {
                int kk = kc * 8 + kq;
                ulonglong2 wv = *(const ulonglong2*)&wS2[(kb + kk) * 16 + rg * 2];
                ulonglong2 xa = *(const ulonglong2*)&bufc[kk * 128 + bg * 4];
                ulonglong2 xb = *(const ulonglong2*)&bufc[kk * 128 + 32 + bg * 4];
                ulonglong2 xc = *(const ulonglong2*)&bufc[kk * 128 + 64 + bg * 4];
                ulonglong2 xd = *(const ulonglong2*)&bufc[kk * 128 + 96 + bg * 4];
                acc[0][0] = fma2(wv.x, xa.x, acc[0][0]);
                acc[0][1] = fma2(wv.x, xa.y, acc[0][1]);
                acc[0][2] = fma2(wv.x, xb.x, acc[0][2]);
                acc[0][3] = fma2(wv.x, xb.y, acc[0][3]);
                acc[0][4] = fma2(wv.x, xc.x, acc[0][4]);
                acc[0][5] = fma2(wv.x, xc.y, acc[0][5]);
                acc[0][6] = fma2(wv.x, xd.x, acc[0][6]);
                acc[0][7] = fma2(wv.x, xd.y, acc[0][7]);
                acc[1][0] = fma2(wv.y, xa.x, acc[1][0]);
                acc[1][1] = fma2(wv.y, xa.y, acc[1][1]);
                acc[1][2] = fma2(wv.y, xb.x, acc[1][2]);
                acc[1][3] = fma2(wv.y, xb.y, acc[1][3]);
                acc[1][4] = fma2(wv.y, xc.x, acc[1][4]);
                acc[1][5] = fma2(wv.y, xc.y, acc[1][5]);
                acc[1][6] = fma2(wv.y, xd.x, acc[1][6]);
                acc[1][7] = fma2(wv.y, xd.y, acc[1][7]);
            }
            __syncthreads();
        }
        #pragma unroll
        for (int r = 0; r < 2; r++)
            #pragma unroll
            for (int j = 0; j < 8; j++)
                part[(kc * 16 + rg * 2 + r) * 64 + (j >> 1) * 16 + bg * 2 + (j & 1)] = acc[r][j];
        __syncthreads();
        {
            const ull* pre0 = (const ull*)&g_gates2[(size_t)(t * G4H + grow0) * BB];
            const ull* pre1 = (const ull*)&g_gates2[(size_t)(t * G4H + grow1) * BB];
            ull s0 = pre0[bp], s1 = pre1[bp];
            #pragma unroll
            for (int q = 0; q < 8; q++) {
                s0 = add2(s0, part[(q * 16 + prow0) * 64 + bp]);
                s1 = add2(s1, part[(q * 16 + prow1) * 64 + bp]);
            }
            ((ull*)gS)[prow0 * 64 + bp] = s0;
            ((ull*)gS)[prow1 * 64 + bp] = s1;
        }
        __syncthreads();
        {
            float* hwr = g_h2T[(t + 1) & 1];
            int hl = tid >> 7, bb2 = tid & 127;
            int hu = hu0 + hl;
            float gi = sigf(gS[(hl * 4 + 0) * BB + bb2]);
            float gf = sigf(gS[(hl * 4 + 1) * BB + bb2]);
            float gg = tanhf(gS[(hl * 4 + 2) * BB + bb2]);
            float go = sigf(gS[(hl * 4 + 3) * BB + bb2]);
            float c = gf * g_c2T[hu * BB + bb2] + gi * gg;
            float h = go * tanhf(c);
            g_c2T[hu * BB + bb2] = c;
            hwr[hu * BB + bb2] = h;
            g_yT[(t * HH + hu) * BB + bb2] = h;
        }
        gbar();
    }
}

// ---------------- final projection ----------------
__global__ void final_kernel(const float* __restrict__ W2, const float* __restrict__ b2,
                             float* __restrict__ out) {
    __shared__ float w_s[128 * 33];
    __shared__ float y_s[32 * 128];
    int t = blockIdx.x;
    int tid = threadIdx.x, tx = tid & 15, ty = tid >> 4;
    int lk = tid & 31, lo0 = tid >> 5;
    int lb = tid & 127, lq = tid >> 7;

    float acc[8][8];
    #pragma unroll
    for (int i = 0; i < 8; i++)
        #pragma unroll
        for (int j = 0; j < 8; j++) acc[i][j] = 0.0f;

    for (int k0 = 0; k0 < HH; k0 += 32) {
        for (int oo = lo0; oo < 128; oo += 8)
            w_s[oo * 33 + lk] = (oo < DOUT) ? W2[oo * HH + k0 + lk] : 0.0f;
        for (int kk = lq; kk < 32; kk += 2)
            y_s[kk * BB + lb] = g_yT[(t * HH + k0 + kk) * BB + lb];
        __syncthreads();
        for (int kk = 0; kk < 32; kk++) {
            float wf[8];
            #pragma unroll
            for (int i = 0; i < 8; i++) wf[i] = w_s[(ty * 8 + i) * 33 + kk];
            float4 xa = *(const float4*)&y_s[kk * 128 + tx * 4];
            float4 xb = *(const float4*)&y_s[kk * 128 + 64 + tx * 4];
            float xf[8] = {xa.x, xa.y, xa.z, xa.w, xb.x, xb.y, xb.z, xb.w};
            #pragma unroll
            for (int i = 0; i < 8; i++)
                #pragma unroll
                for (int j = 0; j < 8; j++) acc[i][j] += wf[i] * xf[j];
        }
        __syncthreads();
    }
    #pragma unroll
    for (int i = 0; i < 8; i++) {
        int o = ty * 8 + i;
        if (o < DOUT) {
            float bi = b2[o];
            #pragma unroll
            for (int j = 0; j < 8; j++) {
                int bb2 = (j >> 2) * 64 + tx * 4 + (j & 3);
                out[(size_t)(bb2 * TT + t) * DOUT + o] = acc[i][j] + bi;
            }
        }
    }
}

// ---------------- epilogue ----------------
__global__ void epi_kernel(float* __restrict__ out) {
    int idx = blockIdx.x * blockDim.x + threadIdx.x;
    if (idx >= BB * HH) return;
    int b = idx / HH, h = idx % HH;
    size_t base = (size_t)BB * TT * DOUT;
    out[base + idx]               = g_h1[idx];
    out[base + BB * HH + idx]     = g_c1T[h * BB + b];
    out[base + 2 * BB * HH + idx] = g_h2T[0][h * BB + b];
    out[base + 3 * BB * HH + idx] = g_c2T[h * BB + b];
}

extern "C" void kernel_launch(void* const* d_in, const int* in_sizes, int n_in,
                              void* d_out, int out_size) {
    const float* x      = (const float*)d_in[0];
    const float* sent   = (const float*)d_in[1];
    const float* h1h    = (const float*)d_in[2];
    const float* h1c    = (const float*)d_in[3];
    const float* h2h    = (const float*)d_in[4];
    const float* h2c    = (const float*)d_in[5];
    const float* Wihc   = (const float*)d_in[6];
    const float* Whhc   = (const float*)d_in[7];
    const float* bcell  = (const float*)d_in[8];
    const float* Wihl   = (const float*)d_in[9];
    const float* Whhl   = (const float*)d_in[10];
    const float* bl     = (const float*)d_in[11];
    const float* W1     = (const float*)d_in[12];
    const float* b1     = (const float*)d_in[13];
    const float* W2     = (const float*)d_in[14];
    const float* b2     = (const float*)d_in[15];
    float* out = (float*)d_out;

    // scanA: wS2 73728 + xS 65536 + gS 8192 + hb 2048 + misc 512 = 150016 B
    size_t smA = (size_t)16 * XDP * 8 + 2 * 8192 * 4 + 16 * BB * 4 + HH * 4 + 128 * 4;
    // scan2: wS2 65536 + xS 65536 + gS 8192 = 139264 B
    size_t sm2 = (size_t)16 * HH * 8 + 2 * 8192 * 4 + 16 * BB * 4;
    cudaFuncSetAttribute(scanA_kernel, cudaFuncAttributeMaxDynamicSharedMemorySize, (int)smA);
    cudaFuncSetAttribute(scan2_kernel, cudaFuncAttributeMaxDynamicSharedMemorySize, (int)sm2);

    int init_n = BB * HH + BB * 3 * KK + TT * DIN * BB + TT * BB;
    init_kernel<<<(init_n + 255) / 256, 256>>>(x, h1h, h1c, h2h, h2c);
    scanA_kernel<<<NBA, NTS, smA>>>(sent, Wihc, Whhc, bcell, W1, b1, Wihl, bl);
    scan2_kernel<<<NB, NTS, sm2>>>(Whhl);
    final_kernel<<<TT, 256>>>(W2, b2, out);
    epi_kernel<<<(BB * HH + 255) / 256, 256>>>(out);
}

// round 10
// speedup vs baseline: 3.6894x; 1.0076x over previous
#include <cuda_runtime.h>
#include <cuda_bf16.h>
#include <math.h>

#define BB   128
#define TT   256
#define SS   64
#define DIN  3
#define HH   512
#define KK   10
#define CSLN 60
#define DOUT 121
#define G4H  2048
#define XD   575   // DIN + CSLN + HH (gemm order: x,win,h)
#define XD1  63    // DIN + CSLN
#define XDP  576   // scan1 permuted+padded: [h 512 | x 3 | win 60 | zero 1]

#define NB   128   // scan blocks (barrier count)
#define NBA  148   // total blocks in fused kernel (all resident)
#define NTS  512

typedef unsigned long long ull;

__device__ __forceinline__ ull pk2(float lo, float hi) {
    ull r; asm("mov.b64 %0,{%1,%2};" : "=l"(r) : "f"(lo), "f"(hi)); return r;
}
__device__ __forceinline__ ull fma2(ull a, ull b, ull c) {
    ull d; asm("fma.rn.f32x2 %0,%1,%2,%3;" : "=l"(d) : "l"(a), "l"(b), "l"(c)); return d;
}
__device__ __forceinline__ ull add2(ull a, ull b) {
    ull d; asm("add.rn.f32x2 %0,%1,%2;" : "=l"(d) : "l"(a), "l"(b)); return d;
}

// ---------------- device scratch ----------------
__device__ __align__(16) float g_h1[BB * HH];
__device__ __align__(16) float g_h1T[2][HH * BB];
__device__ __align__(16) float g_c1T[HH * BB];
__device__ __align__(16) float g_h2T[2][HH * BB];
__device__ __align__(16) float g_c2T[HH * BB];
__device__ __align__(16) float g_p[BB * 3 * KK];
__device__ __align__(16) float g_xw[TT * 64 * BB];   // [t][64: x0..2,win0..59,zero][b]
__device__ __align__(16) float g_h1seqT[TT * HH * BB];
__device__ __align__(16) float g_gates2[TT * G4H * BB];
__device__ __align__(16) float g_yT[TT * HH * BB];
__device__ volatile unsigned g_gen = 0;
__device__ volatile unsigned g_flag[NB * 32];   // padded: one flag per 128B
__device__ unsigned g_ticket = 0;

__device__ __forceinline__ float sigf(float x) { return 1.0f / (1.0f + expf(-x)); }

// flag barrier across the NB scan blocks; target is a monotone generation number
__device__ __forceinline__ void gbar(unsigned target) {
    __syncthreads();
    int tid = threadIdx.x;
    if (blockIdx.x == 0) {
        if (tid == 0) __threadfence();
        if (tid >= 1 && tid < NB) {
            while (g_flag[tid * 32] < target) { }
        }
        __syncthreads();
        if (tid == 0) { __threadfence(); g_gen = target; }
    } else {
        if (tid == 0) {
            __threadfence();
            g_flag[blockIdx.x * 32] = target;
            while (g_gen < target) { }
        }
        __syncthreads();
    }
}

// ---------------- init ----------------
__global__ void init_kernel(const float* __restrict__ x,
                            const float* __restrict__ h1h, const float* __restrict__ h1c,
                            const float* __restrict__ h2h, const float* __restrict__ h2c) {
    int idx = blockIdx.x * blockDim.x + threadIdx.x;
    if (idx == 0) { g_gen = 0; g_ticket = 0; }
    if (idx < NB * 32) g_flag[idx] = 0;
    if (idx < BB * HH) {
        int b = idx / HH, h = idx % HH;
        float v = h1h[idx];
        g_h1[idx] = v;
        g_h1T[0][h * BB + b] = v;
        g_c1T[h * BB + b] = h1c[idx];
        g_h2T[0][h * BB + b] = h2h[idx];
        g_c2T[h * BB + b] = h2c[idx];
    }
    int i2 = idx - BB * HH;
    if (i2 >= 0 && i2 < BB * 3 * KK) g_p[i2] = 0.0f;
    int i3 = idx - BB * HH - BB * 3 * KK;
    if (i3 >= 0 && i3 < TT * DIN * BB) {
        int b = i3 % BB;
        int r = i3 / BB;
        int t = r / DIN, i = r % DIN;
        g_xw[(t * 64 + i) * BB + b] = x[(b * TT + t) * DIN + i];
    }
    int i4 = i3 - TT * DIN * BB;
    if (i4 >= 0 && i4 < TT * BB) {
        int t = i4 / BB, b = i4 % BB;
        g_xw[(t * 64 + 63) * BB + b] = 0.0f;
    }
}

// gemm feature fetch (original order): kg in [0,XD)
__device__ __forceinline__ float fetch_seq(int t, int kg, int bb) {
    if (kg < XD1) return g_xw[(t * 64 + kg) * BB + bb];
    else          return g_h1seqT[(t * HH + (kg - XD1)) * BB + bb];
}

// ---------------- gemm work unit: gates2[t] rows [rt*128, rt*128+128) ----------------
__device__ void gemm_unit(int t, int rt, int tid, char* smraw,
                          const float* __restrict__ W, const float* __restrict__ bias) {
    ull*   a_s = (ull*)smraw;               // [128][33] pairs {w,w}
    float* x_s = (float*)(a_s + 128 * 33);  // [32][128]
    int ty = tid >> 5, tx = tid & 31;

    ull acc[8][2];
    #pragma unroll
    for (int i = 0; i < 8; i++) { acc[i][0] = 0ull; acc[i][1] = 0ull; }

    for (int k0 = 0; k0 < XD; k0 += 32) {
        for (int i = tid; i < 128 * 32; i += NTS) {
            int row = i >> 5, kk = i & 31;
            int k = k0 + kk;
            float w = (k < XD) ? W[(rt * 128 + row) * XD + k] : 0.0f;
            a_s[row * 33 + kk] = pk2(w, w);
        }
        for (int i = tid; i < 32 * 128; i += NTS) {
            int kk = i >> 7, bb = i & 127;
            int k = k0 + kk;
            x_s[i] = (k < XD) ? fetch_seq(t, k, bb) : 0.0f;
        }
        __syncthreads();
        #pragma unroll 4
        for (int kk = 0; kk < 32; kk++) {
            ulonglong2 xv = *(const ulonglong2*)&x_s[kk * 128 + tx * 4];
            #pragma unroll
            for (int i = 0; i < 8; i++) {
                ull w2 = a_s[(ty * 8 + i) * 33 + kk];
                acc[i][0] = fma2(w2, xv.x, acc[i][0]);
                acc[i][1] = fma2(w2, xv.y, acc[i][1]);
            }
        }
        __syncthreads();
    }
    #pragma unroll
    for (int i = 0; i < 8; i++) {
        int row = rt * 128 + ty * 8 + i;
        float bi = bias[row];
        ull bpr = pk2(bi, bi);
        ull* gp = (ull*)&g_gates2[(size_t)(t * G4H + row) * BB];
        gp[tx * 2]     = add2(acc[i][0], bpr);
        gp[tx * 2 + 1] = add2(acc[i][1], bpr);
    }
}

__device__ void steal_loop(int tid, char* smraw,
                           const float* __restrict__ W, const float* __restrict__ bias) {
    __shared__ int sTk;
    for (;;) {
        __syncthreads();
        if (tid == 0) sTk = (int)atomicAdd(&g_ticket, 1u);
        __syncthreads();
        int tk = sTk;
        if (tk >= TT * 16) break;
        int t = tk >> 4, rt = tk & 15;
        if (tid == 0) {
            unsigned need = 2u * t + 2u;
            while (g_gen < need) { }
            __threadfence();
        }
        __syncthreads();
        gemm_unit(t, rt, tid, smraw, W, bias);
    }
}

// ---------------- fused kernel A: scan1 + gemm workers ----------------
__global__ __launch_bounds__(NTS, 1)
void scanA_kernel(const float* __restrict__ sent,
                  const float* __restrict__ W_ih, const float* __restrict__ W_hh,
                  const float* __restrict__ b_cell,
                  const float* __restrict__ W1, const float* __restrict__ b1,
                  const float* __restrict__ W_ihl, const float* __restrict__ b_l) {
    extern __shared__ __align__(16) char smraw[];
    int tid = threadIdx.x;

    if (blockIdx.x < NB) {
        ull*   wS2  = (ull*)smraw;                    // [XDP][16] pairs {w,w}
        float* xS   = (float*)(wS2 + 16 * XDP);       // 2 x [128k][128b] double buffer
        float* gS   = xS + 2 * 16384;                 // [16][128]
        float* hb   = gS + 16 * BB;                   // 512
        float* ipS  = hb + HH;                        // 32
        float* pS   = ipS + 32;                       // 32
        float* phiS = pS + 32;                        // 64
        ull*   part = (ull*)xS;                       // aliases buf0 (64KB)

        int b   = blockIdx.x;
        int hu0 = b * 4;
        int bg = tid & 7, rg = (tid >> 3) & 7, kc = tid >> 6;
        int lane = tid & 31, wid = tid >> 5;
        int rot = b & 3;

        // permuted weights: k<512 -> W_hh col k; k>=512 -> W_ih col (k-512); k=575 pad 0
        for (int i = tid; i < 16 * XDP; i += NTS) {
            int k = i >> 4, r = i & 15;
            int g4 = r & 3, hl = r >> 2;
            int grow = g4 * HH + hu0 + hl;
            float w;
            if (k < HH) w = W_hh[grow * HH + k];
            else { int j = k - HH; w = (j < XD1) ? W_ih[grow * XD1 + j] : 0.0f; }
            wS2[i] = pk2(w, w);
        }
        int prow0 = tid >> 6, prow1 = prow0 + 8;
        int bp = tid & 63;
        float bias0 = b_cell[(prow0 & 3) * HH + hu0 + (prow0 >> 2)];
        float bias1 = b_cell[(prow1 & 3) * HH + hu0 + (prow1 >> 2)];
        ull bpr0 = pk2(bias0, bias0), bpr1 = pk2(bias1, bias1);
        __syncthreads();

        for (int t = 0; t < TT; t++) {
            const float* h1rd  = g_h1T[t & 1];
            const float* xwsrc = g_xw + t * 8192;

            // ---- phase A: attention window for batch b ----
            if (tid < HH) hb[tid] = __ldcg(g_h1 + b * HH + tid);
            __syncthreads();
            for (int j = wid; j < 3 * KK; j += 16) {
                float s = 0.0f;
                const float* w1r = W1 + j * HH;
                #pragma unroll
                for (int m = 0; m < 16; m++) {
                    int id = lane + 32 * m;
                    s += hb[id] * w1r[id];
                }
                for (int o = 16; o > 0; o >>= 1) s += __shfl_down_sync(0xffffffffu, s, o);
                if (lane == 0) ipS[j] = expf(s + b1[j]);
            }
            __syncthreads();
            if (tid < 3 * KK) {
                float pn = ipS[tid];
                if (tid >= 2 * KK) pn -= g_p[b * 3 * KK + tid];
                g_p[b * 3 * KK + tid] = pn;
                pS[tid] = pn;
            }
            __syncthreads();
            if (tid < SS) {
                float u = (float)(tid + 1);
                float s = 0.0f;
                #pragma unroll
                for (int k = 0; k < KK; k++) {
                    float d = pS[2 * KK + k] - u;
                    s += pS[k] * expf(-pS[KK + k] * d * d);
                }
                phiS[tid] = s;
            }
            __syncthreads();
            if (tid < CSLN) {
                float s = 0.0f;
                const float* sb = sent + b * SS * CSLN + tid;
                #pragma unroll 8
                for (int ss = 0; ss < SS; ss++) s += phiS[ss] * sb[ss * CSLN];
                g_xw[(t * 64 + DIN + tid) * BB + b] = s;
            }

            // preload h tile 0 while waiting at the barrier (valid since last step)
            float4 pf[8];
            {
                const float* s0 = h1rd + rot * 16384;
                #pragma unroll
                for (int q = 0; q < 8; q++)
                    pf[q] = __ldcg((const float4*)(s0 + q * 2048 + tid * 4));
            }
            gbar(2u * t + 1u);

            // ---- phase B: 4 x 128-k h tiles + 1 x 64-k xw tile, 1 sync/tile ----
            ull acc[2][8];
            #pragma unroll
            for (int r = 0; r < 2; r++)
                #pragma unroll
                for (int j = 0; j < 8; j++) acc[r][j] = 0ull;

            for (int i = 0; i < 4; i++) {
                float* bufc = xS + (i & 1) * 16384;
                #pragma unroll
                for (int q = 0; q < 8; q++)
                    *(float4*)(bufc + q * 2048 + tid * 4) = pf[q];
                if (i < 3) {
                    const float* sn = h1rd + (((i + 1 + rot) & 3) * 16384);
                    #pragma unroll
                    for (int q = 0; q < 8; q++)
                        pf[q] = __ldcg((const float4*)(sn + q * 2048 + tid * 4));
                } else {
                    #pragma unroll
                    for (int q = 0; q < 4; q++)
                        pf[q] = __ldcg((const float4*)(xwsrc + q * 2048 + tid * 4));
                }
                __syncthreads();
                int kb = ((i + rot) & 3) * 128;
                #pragma unroll 4
                for (int kq = 0; kq < 16; kq++) {
                    int kk = kc * 16 + kq;
                    ulonglong2 wv = *(const ulonglong2*)&wS2[(kb + kk) * 16 + rg * 2];
                    ulonglong2 xa = *(const ulonglong2*)&bufc[kk * 128 + bg * 4];
                    ulonglong2 xb = *(const ulonglong2*)&bufc[kk * 128 + 32 + bg * 4];
                    ulonglong2 xc = *(const ulonglong2*)&bufc[kk * 128 + 64 + bg * 4];
                    ulonglong2 xd = *(const ulonglong2*)&bufc[kk * 128 + 96 + bg * 4];
                    acc[0][0] = fma2(wv.x, xa.x, acc[0][0]);
                    acc[0][1] = fma2(wv.x, xa.y, acc[0][1]);
                    acc[0][2] = fma2(wv.x, xb.x, acc[0][2]);
                    acc[0][3] = fma2(wv.x, xb.y, acc[0][3]);
                    acc[0][4] = fma2(wv.x, xc.x, acc[0][4]);
                    acc[0][5] = fma2(wv.x, xc.y, acc[0][5]);
                    acc[0][6] = fma2(wv.x, xd.x, acc[0][6]);
                    acc[0][7] = fma2(wv.x, xd.y, acc[0][7]);
                    acc[1][0] = fma2(wv.y, xa.x, acc[1][0]);
                    acc[1][1] = fma2(wv.y, xa.y, acc[1][1]);
                    acc[1][2] = fma2(wv.y, xb.x, acc[1][2]);
                    acc[1][3] = fma2(wv.y, xb.y, acc[1][3]);
                    acc[1][4] = fma2(wv.y, xc.x, acc[1][4]);
                    acc[1][5] = fma2(wv.y, xc.y, acc[1][5]);
                    acc[1][6] = fma2(wv.y, xd.x, acc[1][6]);
                    acc[1][7] = fma2(wv.y, xd.y, acc[1][7]);
                }
            }
            {   // last tile: 64 k rows of xw, buffer 0
                float* bufc = xS;
                #pragma unroll
                for (int q = 0; q < 4; q++)
                    *(float4*)(bufc + q * 2048 + tid * 4) = pf[q];
                __syncthreads();
                #pragma unroll 4
                for (int kq = 0; kq < 8; kq++) {
                    int kk = kc * 8 + kq;
                    ulonglong2 wv = *(const ulonglong2*)&wS2[(HH + kk) * 16 + rg * 2];
                    ulonglong2 xa = *(const ulonglong2*)&bufc[kk * 128 + bg * 4];
                    ulonglong2 xb = *(const ulonglong2*)&bufc[kk * 128 + 32 + bg * 4];
                    ulonglong2 xc = *(const ulonglong2*)&bufc[kk * 128 + 64 + bg * 4];
                    ulonglong2 xd = *(const ulonglong2*)&bufc[kk * 128 + 96 + bg * 4];
                    acc[0][0] = fma2(wv.x, xa.x, acc[0][0]);
                    acc[0][1] = fma2(wv.x, xa.y, acc[0][1]);
                    acc[0][2] = fma2(wv.x, xb.x, acc[0][2]);
                    acc[0][3] = fma2(wv.x, xb.y, acc[0][3]);
                    acc[0][4] = fma2(wv.x, xc.x, acc[0][4]);
                    acc[0][5] = fma2(wv.x, xc.y, acc[0][5]);
                    acc[0][6] = fma2(wv.x, xd.x, acc[0][6]);
                    acc[0][7] = fma2(wv.x, xd.y, acc[0][7]);
                    acc[1][0] = fma2(wv.y, xa.x, acc[1][0]);
                    acc[1][1] = fma2(wv.y, xa.y, acc[1][1]);
                    acc[1][2] = fma2(wv.y, xb.x, acc[1][2]);
                    acc[1][3] = fma2(wv.y, xb.y, acc[1][3]);
                    acc[1][4] = fma2(wv.y, xc.x, acc[1][4]);
                    acc[1][5] = fma2(wv.y, xc.y, acc[1][5]);
                    acc[1][6] = fma2(wv.y, xd.x, acc[1][6]);
                    acc[1][7] = fma2(wv.y, xd.y, acc[1][7]);
                }
            }
            __syncthreads();   // all compute done before partials overwrite buffers
            #pragma unroll
            for (int r = 0; r < 2; r++)
                #pragma unroll
                for (int j = 0; j < 8; j++)
                    part[(kc * 16 + rg * 2 + r) * 64 + (j >> 1) * 16 + bg * 2 + (j & 1)] = acc[r][j];
            __syncthreads();
            {
                ull s0 = bpr0, s1 = bpr1;
                #pragma unroll
                for (int q = 0; q < 8; q++) {
                    s0 = add2(s0, part[(q * 16 + prow0) * 64 + bp]);
                    s1 = add2(s1, part[(q * 16 + prow1) * 64 + bp]);
                }
                ((ull*)gS)[prow0 * 64 + bp] = s0;
                ((ull*)gS)[prow1 * 64 + bp] = s1;
            }
            __syncthreads();
            {
                float* h1wr = g_h1T[(t + 1) & 1];
                int hl = tid >> 7, bb2 = tid & 127;
                int hu = hu0 + hl;
                float gi = sigf(gS[(hl * 4 + 0) * BB + bb2]);
                float gf = sigf(gS[(hl * 4 + 1) * BB + bb2]);
                float gg = tanhf(gS[(hl * 4 + 2) * BB + bb2]);
                float go = sigf(gS[(hl * 4 + 3) * BB + bb2]);
                float c = gf * g_c1T[hu * BB + bb2] + gi * gg;
                float h = go * tanhf(c);
                g_c1T[hu * BB + bb2] = c;
                h1wr[hu * BB + bb2] = h;
                g_h1[bb2 * HH + hu] = h;
                g_h1seqT[(t * HH + hu) * BB + bb2] = h;
            }
            gbar(2u * t + 2u);
        }
    }
    steal_loop(tid, smraw, W_ihl, b_l);
}

// ---------------- scan 2: second LSTM ----------------
__global__ __launch_bounds__(NTS, 1)
void scan2_kernel(const float* __restrict__ W_hh_l) {
    extern __shared__ __align__(16) char smraw[];
    ull*   wS2 = (ull*)smraw;              // [512][16] pairs
    float* xS  = (float*)(wS2 + 16 * HH);  // 2 x [128k][128b] double buffer
    float* gS  = xS + 2 * 16384;           // [16][128]
    ull*   part = (ull*)xS;                // aliases buf0

    int tid = threadIdx.x;
    int hu0 = blockIdx.x * 4;
    int bg = tid & 7, rg = (tid >> 3) & 7, kc = tid >> 6;
    int rot = blockIdx.x & 3;

    for (int i = tid; i < 16 * HH; i += NTS) {
        int k = i >> 4, r = i & 15;
        int g4 = r & 3, hl = r >> 2;
        float w = W_hh_l[(g4 * HH + hu0 + hl) * HH + k];
        wS2[i] = pk2(w, w);
    }
    int prow0 = tid >> 6, prow1 = prow0 + 8;
    int bp = tid & 63;
    int grow0 = (prow0 & 3) * HH + hu0 + (prow0 >> 2);
    int grow1 = (prow1 & 3) * HH + hu0 + (prow1 >> 2);
    __syncthreads();

    for (int t = 0; t < TT; t++) {
        const float* hrd = g_h2T[t & 1];
        ull acc[2][8];
        #pragma unroll
        for (int r = 0; r < 2; r++)
            #pragma unroll
            for (int j = 0; j < 8; j++) acc[r][j] = 0ull;

        float4 pf[8];
        {
            const float* s0 = hrd + rot * 16384;
            #pragma unroll
            for (int q = 0; q < 8; q++)
                pf[q] = __ldcg((const float4*)(s0 + q * 2048 + tid * 4));
        }
        for (int i = 0; i < 4; i++) {
            float* bufc = xS + (i & 1) * 16384;
            #pragma unroll
            for (int q = 0; q < 8; q++)
                *(float4*)(bufc + q * 2048 + tid * 4) = pf[q];
            if (i < 3) {
                const float* sn = hrd + (((i + 1 + rot) & 3) * 16384);
                #pragma unroll
                for (int q = 0; q < 8; q++)
                    pf[q] = __ldcg((const float4*)(sn + q * 2048 + tid * 4));
            }
            __syncthreads();
            int kb = ((i + rot) & 3) * 128;
            #pragma unroll 4
            for (int kq = 0; kq < 16; kq++) {
                int kk = kc * 16 + kq;
                ulonglong2 wv = *(const ulonglong2*)&wS2[(kb + kk) * 16 + rg * 2];
                ulonglong2 xa = *(const ulonglong2*)&bufc[kk * 128 + bg * 4];
                ulonglong2 xb = *(const ulonglong2*)&bufc[kk * 128 + 32 + bg * 4];
                ulonglong2 xc = *(const ulonglong2*)&bufc[kk * 128 + 64 + bg * 4];
                ulonglong2 xd = *(const ulonglong2*)&bufc[kk * 128 + 96 + bg * 4];
                acc[0][0] = fma2(wv.x, xa.x, acc[0][0]);
                acc[0][1] = fma2(wv.x, xa.y, acc[0][1]);
                acc[0][2] = fma2(wv.x, xb.x, acc[0][2]);
                acc[0][3] = fma2(wv.x, xb.y, acc[0][3]);
                acc[0][4] = fma2(wv.x, xc.x, acc[0][4]);
                acc[0][5] = fma2(wv.x, xc.y, acc[0][5]);
                acc[0][6] = fma2(wv.x, xd.x, acc[0][6]);
                acc[0][7] = fma2(wv.x, xd.y, acc[0][7]);
                acc[1][0] = fma2(wv.y, xa.x, acc[1][0]);
                acc[1][1] = fma2(wv.y, xa.y, acc[1][1]);
                acc[1][2] = fma2(wv.y, xb.x, acc[1][2]);
                acc[1][3] = fma2(wv.y, xb.y, acc[1][3]);
                acc[1][4] = fma2(wv.y, xc.x, acc[1][4]);
                acc[1][5] = fma2(wv.y, xc.y, acc[1][5]);
                acc[1][6] = fma2(wv.y, xd.x, acc[1][6]);
                acc[1][7] = fma2(wv.y, xd.y, acc[1][7]);
            }
        }
        __syncthreads();
        #pragma unroll
        for (int r = 0; r < 2; r++)
            #pragma unroll
            for (int j = 0; j < 8; j++)
                part[(kc * 16 + rg * 2 + r) * 64 + (j >> 1) * 16 + bg * 2 + (j & 1)] = acc[r][j];
        __syncthreads();
        {
            const ull* pre0 = (const ull*)&g_gates2[(size_t)(t * G4H + grow0) * BB];
            const ull* pre1 = (const ull*)&g_gates2[(size_t)(t * G4H + grow1) * BB];
            ull s0 = pre0[bp], s1 = pre1[bp];
            #pragma unroll
            for (int q = 0; q < 8; q++) {
                s0 = add2(s0, part[(q * 16 + prow0) * 64 + bp]);
                s1 = add2(s1, part[(q * 16 + prow1) * 64 + bp]);
            }
            ((ull*)gS)[prow0 * 64 + bp] = s0;
            ((ull*)gS)[prow1 * 64 + bp] = s1;
        }
        __syncthreads();
        {
            float* hwr = g_h2T[(t + 1) & 1];
            int hl = tid >> 7, bb2 = tid & 127;
            int hu = hu0 + hl;
            float gi = sigf(gS[(hl * 4 + 0) * BB + bb2]);
            float gf = sigf(gS[(hl * 4 + 1) * BB + bb2]);
            float gg = tanhf(gS[(hl * 4 + 2) * BB + bb2]);
            float go = sigf(gS[(hl * 4 + 3) * BB + bb2]);
            float c = gf * g_c2T[hu * BB + bb2] + gi * gg;
            float h = go * tanhf(c);
            g_c2T[hu * BB + bb2] = c;
            hwr[hu * BB + bb2] = h;
            g_yT[(t * HH + hu) * BB + bb2] = h;
        }
        gbar(512u + t + 1u);
    }
}

// ---------------- final projection ----------------
__global__ void final_kernel(const float* __restrict__ W2, const float* __restrict__ b2,
                             float* __restrict__ out) {
    __shared__ float w_s[128 * 33];
    __shared__ float y_s[32 * 128];
    int t = blockIdx.x;
    int tid = threadIdx.x, tx = tid & 15, ty = tid >> 4;
    int lk = tid & 31, lo0 = tid >> 5;
    int lb = tid & 127, lq = tid >> 7;

    float acc[8][8];
    #pragma unroll
    for (int i = 0; i < 8; i++)
        #pragma unroll
        for (int j = 0; j < 8; j++) acc[i][j] = 0.0f;

    for (int k0 = 0; k0 < HH; k0 += 32) {
        for (int oo = lo0; oo < 128; oo += 8)
            w_s[oo * 33 + lk] = (oo < DOUT) ? W2[oo * HH + k0 + lk] : 0.0f;
        for (int kk = lq; kk < 32; kk += 2)
            y_s[kk * BB + lb] = g_yT[(t * HH + k0 + kk) * BB + lb];
        __syncthreads();
        for (int kk = 0; kk < 32; kk++) {
            float wf[8];
            #pragma unroll
            for (int i = 0; i < 8; i++) wf[i] = w_s[(ty * 8 + i) * 33 + kk];
            float4 xa = *(const float4*)&y_s[kk * 128 + tx * 4];
            float4 xb = *(const float4*)&y_s[kk * 128 + 64 + tx * 4];
            float xf[8] = {xa.x, xa.y, xa.z, xa.w, xb.x, xb.y, xb.z, xb.w};
            #pragma unroll
            for (int i = 0; i < 8; i++)
                #pragma unroll
                for (int j = 0; j < 8; j++) acc[i][j] += wf[i] * xf[j];
        }
        __syncthreads();
    }
    #pragma unroll
    for (int i = 0; i < 8; i++) {
        int o = ty * 8 + i;
        if (o < DOUT) {
            float bi = b2[o];
            #pragma unroll
            for (int j = 0; j < 8; j++) {
                int bb2 = (j >> 2) * 64 + tx * 4 + (j & 3);
                out[(size_t)(bb2 * TT + t) * DOUT + o] = acc[i][j] + bi;
            }
        }
    }
}

// ---------------- epilogue ----------------
__global__ void epi_kernel(float* __restrict__ out) {
    int idx = blockIdx.x * blockDim.x + threadIdx.x;
    if (idx >= BB * HH) return;
    int b = idx / HH, h = idx % HH;
    size_t base = (size_t)BB * TT * DOUT;
    out[base + idx]               = g_h1[idx];
    out[base + BB * HH + idx]     = g_c1T[h * BB + b];
    out[base + 2 * BB * HH + idx] = g_h2T[0][h * BB + b];
    out[base + 3 * BB * HH + idx] = g_c2T[h * BB + b];
}

extern "C" void kernel_launch(void* const* d_in, const int* in_sizes, int n_in,
                              void* d_out, int out_size) {
    const float* x      = (const float*)d_in[0];
    const float* sent   = (const float*)d_in[1];
    const float* h1h    = (const float*)d_in[2];
    const float* h1c    = (const float*)d_in[3];
    const float* h2h    = (const float*)d_in[4];
    const float* h2c    = (const float*)d_in[5];
    const float* Wihc   = (const float*)d_in[6];
    const float* Whhc   = (const float*)d_in[7];
    const float* bcell  = (const float*)d_in[8];
    const float* Wihl   = (const float*)d_in[9];
    const float* Whhl   = (const float*)d_in[10];
    const float* bl     = (const float*)d_in[11];
    const float* W1     = (const float*)d_in[12];
    const float* b1     = (const float*)d_in[13];
    const float* W2     = (const float*)d_in[14];
    const float* b2     = (const float*)d_in[15];
    float* out = (float*)d_out;

    // scanA: wS2 73728 + xS 131072 + gS 8192 + hb 2048 + misc 512 = 215552 B
    size_t smA = (size_t)16 * XDP * 8 + 2 * 16384 * 4 + 16 * BB * 4 + HH * 4 + 128 * 4;
    // scan2: wS2 65536 + xS 131072 + gS 8192 = 204800 B
    size_t sm2 = (size_t)16 * HH * 8 + 2 * 16384 * 4 + 16 * BB * 4;
    cudaFuncSetAttribute(scanA_kernel, cudaFuncAttributeMaxDynamicSharedMemorySize, (int)smA);
    cudaFuncSetAttribute(scan2_kernel, cudaFuncAttributeMaxDynamicSharedMemorySize, (int)sm2);

    int init_n = BB * HH + BB * 3 * KK + TT * DIN * BB + TT * BB;
    init_kernel<<<(init_n + 255) / 256, 256>>>(x, h1h, h1c, h2h, h2c);
    scanA_kernel<<<NBA, NTS, smA>>>(sent, Wihc, Whhc, bcell, W1, b1, Wihl, bl);
    scan2_kernel<<<NB, NTS, sm2>>>(Whhl);
    final_kernel<<<TT, 256>>>(W2, b2, out);
    epi_kernel<<<(BB * HH + 255) / 256, 256>>>(out);
}